// round 14
// baseline (speedup 1.0000x reference)
#include <cuda_runtime.h>
#include <cstdint>

// ============================================================================
// NystromAttention — tf32 tensor cores (R8 pipeline) + sim1-softmax fusion
//                    + flash-fused attn3 chain (sim3 -> softmax -> @V)
//   tgemm3: CTA 128x128x32, 4 warps (2x2) of 64x64, 2-stage cp.async (R8)
//   tgemm : CTA 128x64x32 (N=64 tails)
//   sim1s : attn1 = softmax(Q@kl^T) fused (R13)
//   attn3v: a3v = softmax(ql@K^T) @ V, online softmax, attn3 never materialized
// All GEMM inputs are pre-rounded to tf32 by producers.
// ============================================================================

// ---------------- scratch (device globals) ----------------------------------
__device__ float g_xr   [16777216];
__device__ float g_wqkvr[3145728];
__device__ float g_wfcr [1048576];
__device__ float g_Q    [16777216];  // [b,h,n,d] scaled, rounded
__device__ float g_K    [16777216];
__device__ float g_V    [16777216];
__device__ float g_ql   [1048576];   // [bh, 256, 64]
__device__ float g_kl   [1048576];
__device__ float g_attn1[67108864];  // [bh, 4096, 256] (softmaxed)
__device__ float g_attn2[4194304];   // [bh, 256, 256]
__device__ float g_z0   [4194304];
__device__ float g_z1   [4194304];
__device__ float g_az   [4194304];
__device__ float g_t2   [4194304];
__device__ float g_t4   [4194304];
__device__ float g_a3v  [1048576];   // [bh, 256, 64]
__device__ float g_tmp2 [1048576];   // [bh, 256, 64]
__device__ float g_out  [16777216];  // [b,h,n,d]
__device__ float g_outT [16777216];  // [b,n,1024]
__device__ unsigned int g_m1, g_m2;

__device__ __forceinline__ unsigned f2tf(float f) {
    unsigned u;
    asm("cvt.rna.tf32.f32 %0, %1;" : "=r"(u) : "f"(f));
    return u;
}
__device__ __forceinline__ float rndtf(float f) {
    return __uint_as_float(f2tf(f));
}
__device__ __forceinline__ void cp16(unsigned d, const void* s) {
    asm volatile("cp.async.cg.shared.global [%0], [%1], 16;"
                 :: "r"(d), "l"(s) : "memory");
}
#define CP_COMMIT() asm volatile("cp.async.commit_group;" ::: "memory")
#define CP_WAIT0()  asm volatile("cp.async.wait_group 0;" ::: "memory")
#define CP_WAIT1()  asm volatile("cp.async.wait_group 1;" ::: "memory")

#define MMA_TF32(acc, a0,a1,a2,a3, b0,b1)                                     \
    asm volatile(                                                             \
        "mma.sync.aligned.m16n8k8.row.col.f32.tf32.tf32.f32 "                 \
        "{%0,%1,%2,%3}, {%4,%5,%6,%7}, {%8,%9}, {%0,%1,%2,%3};"               \
        : "+f"(acc[0]), "+f"(acc[1]), "+f"(acc[2]), "+f"(acc[3])              \
        : "r"(a0), "r"(a1), "r"(a2), "r"(a3), "r"(b0), "r"(b1))

// ============================================================================
// tgemm3 (exact R8)
// ============================================================================
static constexpr int AW = 128 * 36;
static constexpr int BW_NN = 32 * 136;
static constexpr int BW_NT = 128 * 36;
static constexpr int SMEM3 = (2 * AW + 2 * BW_NT) * 4;  // 73728

template<bool TRANSB, bool EPI, bool BIAS, bool QKVE, bool RND>
__global__ __launch_bounds__(128)
void tgemm3(const float* __restrict__ A, const float* __restrict__ B,
            float* __restrict__ C, const float* __restrict__ E,
            int Kdim, int lda, int ldb, int ldc,
            long long sA, long long sB, long long sC,
            float alpha, float outScale, const float* __restrict__ bias,
            float* __restrict__ qp, float* __restrict__ kp,
            float* __restrict__ vp)
{
    constexpr int BW = TRANSB ? BW_NT : BW_NN;
    extern __shared__ unsigned sh[];
    unsigned* Ash = sh;
    unsigned* Bsh = sh + 2 * AW;

    const float* Ab = A + (long long)blockIdx.z * sA;
    const float* Bb = B + (long long)blockIdx.z * sB;
    float*       Cb = C + (long long)blockIdx.z * sC;
    const float* Eb = EPI ? (E + (long long)blockIdx.z * sC) : nullptr;

    const int row0 = blockIdx.y * 128;
    const int col0 = blockIdx.x * 128;
    const int t    = threadIdx.x;
    const int lane = t & 31;
    const int w    = t >> 5;
    const int wm   = w & 1;
    const int wn   = w >> 1;
    const int g    = lane >> 2;
    const int tg   = lane & 3;

    const unsigned aBase = (unsigned)__cvta_generic_to_shared(Ash);
    const unsigned bBase = (unsigned)__cvta_generic_to_shared(Bsh);

    auto issue = [&](int k0, int st) {
        unsigned ab = aBase + st * (AW * 4);
        #pragma unroll
        for (int l = 0; l < 8; l++) {
            int c  = t + l * 128;
            int r  = c >> 3;
            int kq = (c & 7) << 2;
            cp16(ab + (unsigned)(r * 36 + kq) * 4,
                 Ab + (long long)(row0 + r) * lda + k0 + kq);
        }
        unsigned bb = bBase + st * (BW * 4);
        #pragma unroll
        for (int l = 0; l < 8; l++) {
            int c = t + l * 128;
            if (!TRANSB) {
                int k  = c >> 5;
                int n4 = (c & 31) << 2;
                cp16(bb + (unsigned)(k * 136 + n4) * 4,
                     Bb + (long long)(k0 + k) * ldb + col0 + n4);
            } else {
                int j  = c >> 3;
                int kq = (c & 7) << 2;
                cp16(bb + (unsigned)(j * 36 + kq) * 4,
                     Bb + (long long)(col0 + j) * ldb + k0 + kq);
            }
        }
        CP_COMMIT();
    };

    float acc[4][8][4];
    #pragma unroll
    for (int mi = 0; mi < 4; mi++)
        #pragma unroll
        for (int ni = 0; ni < 8; ni++)
            #pragma unroll
            for (int q = 0; q < 4; q++) acc[mi][ni][q] = 0.f;

    issue(0, 0);

    int si = 0;
    for (int k0 = 0; k0 < Kdim; k0 += 32) {
        bool more = (k0 + 32 < Kdim);
        if (more) { issue(k0 + 32, si ^ 1); CP_WAIT1(); }
        else      { CP_WAIT0(); }
        __syncthreads();

        const unsigned* Ap = Ash + si * AW;
        const unsigned* Bp = Bsh + si * BW;
        #pragma unroll
        for (int ks = 0; ks < 4; ks++) {
            const int kk = ks * 8;
            unsigned af[4][4], bf[8][2];
            #pragma unroll
            for (int mi = 0; mi < 4; mi++) {
                int rb = wm * 64 + mi * 16;
                af[mi][0] = Ap[(rb + g    ) * 36 + kk + tg];
                af[mi][1] = Ap[(rb + 8 + g) * 36 + kk + tg];
                af[mi][2] = Ap[(rb + g    ) * 36 + kk + 4 + tg];
                af[mi][3] = Ap[(rb + 8 + g) * 36 + kk + 4 + tg];
            }
            #pragma unroll
            for (int ni = 0; ni < 8; ni++) {
                int cb = wn * 64 + ni * 8;
                if (TRANSB) {
                    bf[ni][0] = Bp[(cb + g) * 36 + kk + tg];
                    bf[ni][1] = Bp[(cb + g) * 36 + kk + 4 + tg];
                } else {
                    bf[ni][0] = Bp[(kk + tg) * 136 + cb + g];
                    bf[ni][1] = Bp[(kk + 4 + tg) * 136 + cb + g];
                }
            }
            #pragma unroll
            for (int mi = 0; mi < 4; mi++)
                #pragma unroll
                for (int ni = 0; ni < 8; ni++)
                    MMA_TF32(acc[mi][ni],
                             af[mi][0], af[mi][1], af[mi][2], af[mi][3],
                             bf[ni][0], bf[ni][1]);
        }
        __syncthreads();
        si ^= 1;
    }

    #pragma unroll
    for (int mi = 0; mi < 4; mi++) {
        int r = row0 + wm * 64 + mi * 16 + g;
        #pragma unroll
        for (int ni = 0; ni < 8; ni++) {
            int c = col0 + wn * 64 + ni * 8 + 2 * tg;
            float v00 = acc[mi][ni][0], v01 = acc[mi][ni][1];
            float v10 = acc[mi][ni][2], v11 = acc[mi][ni][3];
            if (QKVE) {
                int which = c >> 10, hh = (c >> 6) & 15, d = c & 63;
                float sc = (which == 0) ? 0.125f : 1.f;
                float* dst = (which == 0) ? qp : ((which == 1) ? kp : vp);
                long long base =
                    (((long long)((r >> 12) * 16 + hh)) * 4096 + (r & 4095)) * 64 + d;
                *reinterpret_cast<float2*>(dst + base) =
                    make_float2(rndtf(v00 * sc), rndtf(v01 * sc));
                *reinterpret_cast<float2*>(dst + base + 512) =
                    make_float2(rndtf(v10 * sc), rndtf(v11 * sc));
                continue;
            }
            if (EPI) {
                float2 e0 = *reinterpret_cast<const float2*>(
                    Eb + (long long)r * ldc + c);
                float2 e1 = *reinterpret_cast<const float2*>(
                    Eb + (long long)(r + 8) * ldc + c);
                v00 = (alpha * e0.x - v00) * outScale;
                v01 = (alpha * e0.y - v01) * outScale;
                v10 = (alpha * e1.x - v10) * outScale;
                v11 = (alpha * e1.y - v11) * outScale;
            } else {
                float b0 = 0.f, b1 = 0.f;
                if (BIAS) { b0 = bias[c]; b1 = bias[c + 1]; }
                v00 = v00 * outScale + b0;  v01 = v01 * outScale + b1;
                v10 = v10 * outScale + b0;  v11 = v11 * outScale + b1;
            }
            if (RND) {
                v00 = rndtf(v00); v01 = rndtf(v01);
                v10 = rndtf(v10); v11 = rndtf(v11);
            }
            *reinterpret_cast<float2*>(Cb + (long long)r * ldc + c) =
                make_float2(v00, v01);
            *reinterpret_cast<float2*>(Cb + (long long)(r + 8) * ldc + c) =
                make_float2(v10, v11);
        }
    }
}

// ============================================================================
// sim1s (exact R13): attn1 = softmax(Q @ kl^T), 64 full rows per CTA
// ============================================================================
static constexpr int S_AW = 2 * 64 * 36;
static constexpr int S_BW = 2 * 256 * 36;
static constexpr int SMEMS = (S_AW + S_BW) * 4;   // 92160

__global__ __launch_bounds__(256, 2)
void sim1s(const float* __restrict__ Q, const float* __restrict__ KL,
           float* __restrict__ OUT)
{
    extern __shared__ unsigned sh[];
    unsigned* Ash = sh;
    unsigned* Bsh = sh + S_AW;
    unsigned* Ss  = Bsh;

    const int bh   = blockIdx.y;
    const int row0 = blockIdx.x * 64;
    const int t    = threadIdx.x;
    const int lane = t & 31;
    const int w    = t >> 5;
    const int wm   = w & 1;
    const int wn   = w >> 1;
    const int g    = lane >> 2;
    const int tg   = lane & 3;

    const float* Qb  = Q  + (long long)bh * 262144 + (long long)row0 * 64;
    const float* KLb = KL + (long long)bh * 16384;
    float*       Ob  = OUT + (long long)bh * 1048576 + (long long)row0 * 256;

    const unsigned aBase = (unsigned)__cvta_generic_to_shared(Ash);
    const unsigned bBase = (unsigned)__cvta_generic_to_shared(Bsh);

    #pragma unroll
    for (int l = 0; l < 4; l++) {
        int idx = t + l * 256;
        int r  = idx >> 4;
        int k0 = (idx & 15) << 2;
        cp16(aBase + (unsigned)((k0 >> 5) * 2304 + r * 36 + (k0 & 31)) * 4,
             Qb + r * 64 + k0);
    }
    #pragma unroll
    for (int l = 0; l < 16; l++) {
        int idx = t + l * 256;
        int n  = idx >> 4;
        int k0 = (idx & 15) << 2;
        cp16(bBase + (unsigned)((k0 >> 5) * 9216 + n * 36 + (k0 & 31)) * 4,
             KLb + n * 64 + k0);
    }
    CP_COMMIT();
    CP_WAIT0();
    __syncthreads();

    float acc[2][8][4];
    #pragma unroll
    for (int mi = 0; mi < 2; mi++)
        #pragma unroll
        for (int ni = 0; ni < 8; ni++)
            #pragma unroll
            for (int q = 0; q < 4; q++) acc[mi][ni][q] = 0.f;

    #pragma unroll
    for (int ch = 0; ch < 2; ch++) {
        const unsigned* Ap = Ash + ch * 2304;
        const unsigned* Bp = Bsh + ch * 9216;
        #pragma unroll
        for (int ks = 0; ks < 4; ks++) {
            const int kk = ks * 8;
            unsigned af[2][4], bf[8][2];
            #pragma unroll
            for (int mi = 0; mi < 2; mi++) {
                int rb = wm * 32 + mi * 16;
                af[mi][0] = Ap[(rb + g    ) * 36 + kk + tg];
                af[mi][1] = Ap[(rb + 8 + g) * 36 + kk + tg];
                af[mi][2] = Ap[(rb + g    ) * 36 + kk + 4 + tg];
                af[mi][3] = Ap[(rb + 8 + g) * 36 + kk + 4 + tg];
            }
            #pragma unroll
            for (int ni = 0; ni < 8; ni++) {
                int cb = wn * 64 + ni * 8;
                bf[ni][0] = Bp[(cb + g) * 36 + kk + tg];
                bf[ni][1] = Bp[(cb + g) * 36 + kk + 4 + tg];
            }
            #pragma unroll
            for (int mi = 0; mi < 2; mi++)
                #pragma unroll
                for (int ni = 0; ni < 8; ni++)
                    MMA_TF32(acc[mi][ni],
                             af[mi][0], af[mi][1], af[mi][2], af[mi][3],
                             bf[ni][0], bf[ni][1]);
        }
    }
    __syncthreads();

    #pragma unroll
    for (int mi = 0; mi < 2; mi++) {
        int r = wm * 32 + mi * 16 + g;
        #pragma unroll
        for (int ni = 0; ni < 8; ni++) {
            int c = wn * 64 + ni * 8 + 2 * tg;
            unsigned* p0 = Ss + r * 260 + c;
            p0[0] = __float_as_uint(acc[mi][ni][0]);
            p0[1] = __float_as_uint(acc[mi][ni][1]);
            unsigned* p1 = Ss + (r + 8) * 260 + c;
            p1[0] = __float_as_uint(acc[mi][ni][2]);
            p1[1] = __float_as_uint(acc[mi][ni][3]);
        }
    }
    __syncthreads();

    #pragma unroll
    for (int rr = 0; rr < 8; rr++) {
        int r = w * 8 + rr;
        float v[8];
        float mx = -1e30f;
        #pragma unroll
        for (int i = 0; i < 8; i++) {
            v[i] = __uint_as_float(Ss[r * 260 + lane + 32 * i]);
            mx = fmaxf(mx, v[i]);
        }
        #pragma unroll
        for (int o = 16; o > 0; o >>= 1)
            mx = fmaxf(mx, __shfl_xor_sync(0xffffffffu, mx, o));
        float s = 0.f;
        #pragma unroll
        for (int i = 0; i < 8; i++) { v[i] = expf(v[i] - mx); s += v[i]; }
        #pragma unroll
        for (int o = 16; o > 0; o >>= 1)
            s += __shfl_xor_sync(0xffffffffu, s, o);
        float inv = 1.f / s;
        #pragma unroll
        for (int i = 0; i < 8; i++)
            Ob[r * 256 + lane + 32 * i] = rndtf(v[i] * inv);
    }
}

// ============================================================================
// attn3v: a3v[bh,128m,64d] = softmax_n(ql @ K^T) @ V with online softmax.
// CTA: (mtile, bh); 256 threads (8 warps: 4 row-groups x 2 col-groups, 32x32).
// Streams 64-token chunks of K/V (double-buffered cp.async). S/P in smem.
// ============================================================================
static constexpr int F_QLW = 2 * 128 * 36;          // 9216
static constexpr int F_KST = 2 * 64 * 36;           // 4608 (K part of a stage)
static constexpr int F_VST = 2 * 32 * 72;           // 4608 (V part)
static constexpr int F_STG = F_KST + F_VST;         // 9216 per stage
static constexpr int F_PW  = 2 * 128 * 36;          // 9216
static constexpr int SMEMA = (F_QLW + 2 * F_STG + F_PW + 3 * 128) * 4; // 148992

__global__ __launch_bounds__(256, 1)
void attn3v(const float* __restrict__ QL, const float* __restrict__ K,
            const float* __restrict__ V, float* __restrict__ OUT)
{
    extern __shared__ unsigned sh[];
    unsigned* QLs = sh;                       // [2][128][36]
    unsigned* KVs = sh + F_QLW;               // 2 stages of (K | V)
    unsigned* Ps  = sh + F_QLW + 2 * F_STG;   // [2][128][36]
    float* Ms = (float*)(Ps + F_PW);
    float* Ls = Ms + 128;
    float* As = Ls + 128;

    const int bh = blockIdx.y;
    const int m0 = blockIdx.x * 128;
    const int t    = threadIdx.x;
    const int lane = t & 31;
    const int w    = t >> 5;
    const int wm   = w >> 1;        // 4 row groups of 32
    const int wn   = w & 1;         // 2 col groups of 32
    const int g    = lane >> 2;
    const int tg   = lane & 3;

    const float* Qb = QL + (long long)bh * 16384 + (long long)m0 * 64;
    const float* Kb = K  + (long long)bh * 262144;
    const float* Vb = V  + (long long)bh * 262144;
    float*       Ob = OUT + (long long)bh * 16384 + (long long)m0 * 64;

    const unsigned qlB = (unsigned)__cvta_generic_to_shared(QLs);
    const unsigned kvB = (unsigned)__cvta_generic_to_shared(KVs);

    if (t < 128) { Ms[t] = -1e30f; Ls[t] = 0.f; }

    auto issueKV = [&](int n0, int st) {
        unsigned kb = kvB + (unsigned)(st * F_STG) * 4;
        #pragma unroll
        for (int l = 0; l < 4; l++) {
            int idx = t + l * 256;          // 0..1023
            int n  = idx >> 4;              // token 0..63
            int kq = (idx & 15) << 2;       // 0..60
            cp16(kb + (unsigned)((kq >> 5) * 2304 + n * 36 + (kq & 31)) * 4,
                 Kb + (long long)(n0 + n) * 64 + kq);
        }
        unsigned vb = kb + (unsigned)F_KST * 4;
        #pragma unroll
        for (int l = 0; l < 4; l++) {
            int idx = t + l * 256;
            int k  = idx >> 4;              // token 0..63
            int dq = (idx & 15) << 2;       // 0..60
            cp16(vb + (unsigned)((k >> 5) * 2304 + (k & 31) * 72 + dq) * 4,
                 Vb + (long long)(n0 + k) * 64 + dq);
        }
        CP_COMMIT();
    };

    // prologue: ql + first KV chunk in one group
    #pragma unroll
    for (int l = 0; l < 8; l++) {
        int idx = t + l * 256;              // 0..2047
        int r  = idx >> 4;                  // 0..127
        int kq = (idx & 15) << 2;
        cp16(qlB + (unsigned)((kq >> 5) * 4608 + r * 36 + (kq & 31)) * 4,
             Qb + (long long)r * 64 + kq);
    }
    issueKV(0, 0);

    float accO[2][4][4];
    #pragma unroll
    for (int mi = 0; mi < 2; mi++)
        #pragma unroll
        for (int ni = 0; ni < 4; ni++)
            #pragma unroll
            for (int q = 0; q < 4; q++) accO[mi][ni][q] = 0.f;

    for (int it = 0; it < 64; it++) {
        CP_WAIT0();
        __syncthreads();                     // stage it&1 ready; prev O-mma done
        if (it + 1 < 64) issueKV((it + 1) * 64, (it + 1) & 1);

        const unsigned* Kst = KVs + (it & 1) * F_STG;
        const unsigned* Vst = Kst + F_KST;

        // ---- S = ql @ K^T  (128x64, warp 32x32)
        float accS[2][4][4];
        #pragma unroll
        for (int mi = 0; mi < 2; mi++)
            #pragma unroll
            for (int ni = 0; ni < 4; ni++)
                #pragma unroll
                for (int q = 0; q < 4; q++) accS[mi][ni][q] = 0.f;

        #pragma unroll
        for (int ch = 0; ch < 2; ch++) {
            const unsigned* Ap = QLs + ch * 4608;
            const unsigned* Bp = Kst + ch * 2304;
            #pragma unroll
            for (int ks = 0; ks < 4; ks++) {
                const int kk = ks * 8;
                unsigned af[2][4], bf[4][2];
                #pragma unroll
                for (int mi = 0; mi < 2; mi++) {
                    int rb = wm * 32 + mi * 16;
                    af[mi][0] = Ap[(rb + g    ) * 36 + kk + tg];
                    af[mi][1] = Ap[(rb + 8 + g) * 36 + kk + tg];
                    af[mi][2] = Ap[(rb + g    ) * 36 + kk + 4 + tg];
                    af[mi][3] = Ap[(rb + 8 + g) * 36 + kk + 4 + tg];
                }
                #pragma unroll
                for (int ni = 0; ni < 4; ni++) {
                    int cb = wn * 32 + ni * 8;
                    bf[ni][0] = Bp[(cb + g) * 36 + kk + tg];
                    bf[ni][1] = Bp[(cb + g) * 36 + kk + 4 + tg];
                }
                #pragma unroll
                for (int mi = 0; mi < 2; mi++)
                    #pragma unroll
                    for (int ni = 0; ni < 4; ni++)
                        MMA_TF32(accS[mi][ni],
                                 af[mi][0], af[mi][1], af[mi][2], af[mi][3],
                                 bf[ni][0], bf[ni][1]);
            }
        }

        // ---- stash raw S into Ps (A-operand layout, k = token)
        #pragma unroll
        for (int mi = 0; mi < 2; mi++) {
            int r = wm * 32 + mi * 16 + g;
            #pragma unroll
            for (int ni = 0; ni < 4; ni++) {
                int c = wn * 32 + ni * 8 + 2 * tg;
                unsigned* p0 = Ps + (c >> 5) * 4608 + r * 36 + (c & 31);
                p0[0] = __float_as_uint(accS[mi][ni][0]);
                p0[1] = __float_as_uint(accS[mi][ni][1]);
                unsigned* p1 = Ps + (c >> 5) * 4608 + (r + 8) * 36 + (c & 31);
                p1[0] = __float_as_uint(accS[mi][ni][2]);
                p1[1] = __float_as_uint(accS[mi][ni][3]);
            }
        }
        __syncthreads();

        // ---- online softmax (warp w: rows w*16 .. w*16+15)
        #pragma unroll
        for (int rr = 0; rr < 16; rr++) {
            int r = w * 16 + rr;
            float v0 = __uint_as_float(Ps[          r * 36 + lane]);
            float v1 = __uint_as_float(Ps[4608 + r * 36 + lane]);
            float mx = fmaxf(v0, v1);
            #pragma unroll
            for (int o = 16; o > 0; o >>= 1)
                mx = fmaxf(mx, __shfl_xor_sync(0xffffffffu, mx, o));
            float Mold = Ms[r];
            float Mnew = fmaxf(Mold, mx);
            float e0 = expf(v0 - Mnew), e1 = expf(v1 - Mnew);
            float s = e0 + e1;
            #pragma unroll
            for (int o = 16; o > 0; o >>= 1)
                s += __shfl_xor_sync(0xffffffffu, s, o);
            if (lane == 0) {
                float a = expf(Mold - Mnew);
                As[r] = a;
                Ls[r] = Ls[r] * a + s;
                Ms[r] = Mnew;
            }
            Ps[          r * 36 + lane] = f2tf(e0);
            Ps[4608 + r * 36 + lane] = f2tf(e1);
        }
        __syncthreads();

        // ---- rescale O by alpha, then O += P @ V
        #pragma unroll
        for (int mi = 0; mi < 2; mi++) {
            int r = wm * 32 + mi * 16 + g;
            float a0 = As[r], a1 = As[r + 8];
            #pragma unroll
            for (int ni = 0; ni < 4; ni++) {
                accO[mi][ni][0] *= a0; accO[mi][ni][1] *= a0;
                accO[mi][ni][2] *= a1; accO[mi][ni][3] *= a1;
            }
        }
        #pragma unroll
        for (int ch = 0; ch < 2; ch++) {
            const unsigned* Ap = Ps + ch * 4608;
            const unsigned* Bp = Vst + ch * 2304;
            #pragma unroll
            for (int ks = 0; ks < 4; ks++) {
                const int kk = ks * 8;
                unsigned af[2][4], bf[4][2];
                #pragma unroll
                for (int mi = 0; mi < 2; mi++) {
                    int rb = wm * 32 + mi * 16;
                    af[mi][0] = Ap[(rb + g    ) * 36 + kk + tg];
                    af[mi][1] = Ap[(rb + 8 + g) * 36 + kk + tg];
                    af[mi][2] = Ap[(rb + g    ) * 36 + kk + 4 + tg];
                    af[mi][3] = Ap[(rb + 8 + g) * 36 + kk + 4 + tg];
                }
                #pragma unroll
                for (int ni = 0; ni < 4; ni++) {
                    int cb = wn * 32 + ni * 8;
                    bf[ni][0] = Bp[(kk + tg) * 72 + cb + g];
                    bf[ni][1] = Bp[(kk + 4 + tg) * 72 + cb + g];
                }
                #pragma unroll
                for (int mi = 0; mi < 2; mi++)
                    #pragma unroll
                    for (int ni = 0; ni < 4; ni++)
                        MMA_TF32(accO[mi][ni],
                                 af[mi][0], af[mi][1], af[mi][2], af[mi][3],
                                 bf[ni][0], bf[ni][1]);
            }
        }
    }

    // ---- finalize: O /= L, write fp32
    #pragma unroll
    for (int mi = 0; mi < 2; mi++) {
        int r = wm * 32 + mi * 16 + g;
        float i0 = 1.f / Ls[r], i1 = 1.f / Ls[r + 8];
        #pragma unroll
        for (int ni = 0; ni < 4; ni++) {
            int c = wn * 32 + ni * 8 + 2 * tg;
            *reinterpret_cast<float2*>(Ob + (long long)r * 64 + c) =
                make_float2(accO[mi][ni][0] * i0, accO[mi][ni][1] * i0);
            *reinterpret_cast<float2*>(Ob + (long long)(r + 8) * 64 + c) =
                make_float2(accO[mi][ni][2] * i1, accO[mi][ni][3] * i1);
        }
    }
}

// ============================================================================
// tgemm: CTA 128x64x32, 8 warps (4x2), warp 32x32 — N=64 tails
// ============================================================================
__global__ __launch_bounds__(256)
void tgemm(const float* __restrict__ A, const float* __restrict__ B,
           float* __restrict__ C, int Kdim, int lda, int ldb, int ldc,
           long long sA, long long sB, long long sC)
{
    extern __shared__ unsigned sh[];
    unsigned* As = sh;
    unsigned* Bs = sh + 2 * 4608;

    const float* Ab = A + (long long)blockIdx.z * sA;
    const float* Bb = B + (long long)blockIdx.z * sB;
    float*       Cb = C + (long long)blockIdx.z * sC;

    const int row0 = blockIdx.y * 128;
    const int col0 = blockIdx.x * 64;
    const int t    = threadIdx.x;
    const int lane = t & 31;
    const int w    = t >> 5;
    const int wm   = w & 3;
    const int wn   = w >> 2;
    const int g    = lane >> 2;
    const int tg   = lane & 3;

    float4 aR[4];
    float4 bR[2];

    auto ldA = [&](int k0) {
        #pragma unroll
        for (int l = 0; l < 4; l++) {
            int idx = t + l * 256;
            int r   = idx >> 3;
            int kq  = (idx & 7) << 2;
            aR[l] = *reinterpret_cast<const float4*>(
                Ab + (long long)(row0 + r) * lda + k0 + kq);
        }
    };
    auto stA = [&](int st) {
        unsigned* Ap = As + st * 4608;
        #pragma unroll
        for (int l = 0; l < 4; l++) {
            int idx = t + l * 256;
            int r   = idx >> 3;
            int kq  = (idx & 7) << 2;
            uint4 u = make_uint4(f2tf(aR[l].x), f2tf(aR[l].y),
                                 f2tf(aR[l].z), f2tf(aR[l].w));
            *reinterpret_cast<uint4*>(Ap + r * 36 + kq) = u;
        }
    };
    auto ldB = [&](int k0) {
        #pragma unroll
        for (int l = 0; l < 2; l++) {
            int idx = t + l * 256;
            int r  = idx >> 4;
            int cq = (idx & 15) << 2;
            bR[l] = *reinterpret_cast<const float4*>(
                Bb + (long long)(k0 + r) * ldb + col0 + cq);
        }
    };
    auto stB = [&](int st) {
        unsigned* Bp = Bs + st * 2304;
        #pragma unroll
        for (int l = 0; l < 2; l++) {
            int idx = t + l * 256;
            int r  = idx >> 4;
            int cq = (idx & 15) << 2;
            uint4 u = make_uint4(f2tf(bR[l].x), f2tf(bR[l].y),
                                 f2tf(bR[l].z), f2tf(bR[l].w));
            *reinterpret_cast<uint4*>(Bp + r * 72 + cq) = u;
        }
    };

    float acc[2][4][4];
    #pragma unroll
    for (int mi = 0; mi < 2; mi++)
        #pragma unroll
        for (int ni = 0; ni < 4; ni++)
            #pragma unroll
            for (int q = 0; q < 4; q++) acc[mi][ni][q] = 0.f;

    ldA(0); ldB(0);
    stA(0); stB(0);
    __syncthreads();

    int s = 0;
    for (int k0 = 0; k0 < Kdim; k0 += 32) {
        bool more = (k0 + 32 < Kdim);
        if (more) { ldA(k0 + 32); ldB(k0 + 32); }

        const unsigned* Ap = As + s * 4608;
        const unsigned* Bp = Bs + s * 2304;
        #pragma unroll
        for (int ks = 0; ks < 4; ks++) {
            const int kk = ks * 8;
            unsigned af[2][4], bf[4][2];
            #pragma unroll
            for (int mi = 0; mi < 2; mi++) {
                int rb = wm * 32 + mi * 16;
                af[mi][0] = Ap[(rb + g    ) * 36 + kk + tg];
                af[mi][1] = Ap[(rb + 8 + g) * 36 + kk + tg];
                af[mi][2] = Ap[(rb + g    ) * 36 + kk + 4 + tg];
                af[mi][3] = Ap[(rb + 8 + g) * 36 + kk + 4 + tg];
            }
            #pragma unroll
            for (int ni = 0; ni < 4; ni++) {
                int cb = wn * 32 + ni * 8;
                bf[ni][0] = Bp[(kk + tg) * 72 + cb + g];
                bf[ni][1] = Bp[(kk + 4 + tg) * 72 + cb + g];
            }
            #pragma unroll
            for (int mi = 0; mi < 2; mi++)
                #pragma unroll
                for (int ni = 0; ni < 4; ni++)
                    MMA_TF32(acc[mi][ni],
                             af[mi][0], af[mi][1], af[mi][2], af[mi][3],
                             bf[ni][0], bf[ni][1]);
        }

        if (more) {
            stA(s ^ 1); stB(s ^ 1);
            __syncthreads();
        }
        s ^= 1;
    }

    #pragma unroll
    for (int mi = 0; mi < 2; mi++) {
        int r = row0 + wm * 32 + mi * 16 + g;
        #pragma unroll
        for (int ni = 0; ni < 4; ni++) {
            int c = col0 + wn * 32 + ni * 8 + 2 * tg;
            *reinterpret_cast<float2*>(Cb + (long long)r * ldc + c) =
                make_float2(acc[mi][ni][0], acc[mi][ni][1]);
            *reinterpret_cast<float2*>(Cb + (long long)(r + 8) * ldc + c) =
                make_float2(acc[mi][ni][2], acc[mi][ni][3]);
        }
    }
}

// ---------------- elementwise / reductions ---------------------------------
__global__ void round_kernel(const float* __restrict__ src,
                             float* __restrict__ dst, int n4)
{
    int i = blockIdx.x * 256 + threadIdx.x;
    if (i >= n4) return;
    float4 v = reinterpret_cast<const float4*>(src)[i];
    v.x = rndtf(v.x); v.y = rndtf(v.y); v.z = rndtf(v.z); v.w = rndtf(v.w);
    reinterpret_cast<float4*>(dst)[i] = v;
}

__global__ void landmarks_kernel(const float* __restrict__ Q,
                                 const float* __restrict__ K,
                                 float* __restrict__ ql, float* __restrict__ kl)
{
    int i = blockIdx.x * 256 + threadIdx.x;
    int d = i & 63;
    int m = (i >> 6) & 255;
    int bh = i >> 14;
    long long base = ((long long)bh * 4096 + m * 16) * 64 + d;
    float sq = 0.f, sk = 0.f;
    #pragma unroll
    for (int j = 0; j < 16; j++) {
        sq += Q[base + j * 64];
        sk += K[base + j * 64];
    }
    ql[i] = rndtf(sq * 0.0625f);
    kl[i] = rndtf(sk * 0.0625f);
}

__global__ void softmax256_kernel(float* __restrict__ data, int rows)
{
    int gw   = (int)((blockIdx.x * (long long)blockDim.x + threadIdx.x) >> 5);
    int lane = threadIdx.x & 31;
    if (gw >= rows) return;
    float* p = data + (long long)gw * 256;
    float v[8];
    float mx = -1e30f;
    #pragma unroll
    for (int i = 0; i < 8; i++) { v[i] = p[lane + 32 * i]; mx = fmaxf(mx, v[i]); }
    #pragma unroll
    for (int o = 16; o > 0; o >>= 1) mx = fmaxf(mx, __shfl_xor_sync(0xffffffffu, mx, o));
    float s = 0.f;
    #pragma unroll
    for (int i = 0; i < 8; i++) { v[i] = expf(v[i] - mx); s += v[i]; }
    #pragma unroll
    for (int o = 16; o > 0; o >>= 1) s += __shfl_xor_sync(0xffffffffu, s, o);
    float inv = 1.f / s;
    #pragma unroll
    for (int i = 0; i < 8; i++) p[lane + 32 * i] = rndtf(v[i] * inv);
}

__global__ void mp_reset_kernel() { g_m1 = 0u; g_m2 = 0u; }

__global__ void mp_reduce_kernel(const float* __restrict__ a)
{
    int bh = blockIdx.x;
    int j  = threadIdx.x;
    const float* p = a + (long long)bh * 65536;
    float rs = 0.f, cs = 0.f;
    for (int i = 0; i < 256; i++) {
        rs += fabsf(p[j * 256 + i]);
        cs += fabsf(p[i * 256 + j]);
    }
    __shared__ float r1[256], r2[256];
    r1[j] = rs; r2[j] = cs; __syncthreads();
    for (int s = 128; s > 0; s >>= 1) {
        if (j < s) { r1[j] = fmaxf(r1[j], r1[j + s]); r2[j] = fmaxf(r2[j], r2[j + s]); }
        __syncthreads();
    }
    if (j == 0) {
        atomicMax(&g_m1, __float_as_uint(r1[0]));
        atomicMax(&g_m2, __float_as_uint(r2[0]));
    }
}

__global__ void mp_init_kernel(const float* __restrict__ a, float* __restrict__ z)
{
    long long i = (long long)blockIdx.x * 256 + threadIdx.x;
    int col = (int)(i & 255);
    int row = (int)((i >> 8) & 255);
    long long bh = i >> 16;
    float denom = __uint_as_float(g_m1) * __uint_as_float(g_m2);
    z[i] = rndtf(a[bh * 65536 + (long long)col * 256 + row] / denom);
}

// fused: depthwise residual conv (K=13, pad 6) + [b,h,n,d] -> [b,n,h*64+d]
__global__ void conv_tr_kernel(const float* __restrict__ src,
                               const float* __restrict__ w,
                               float* __restrict__ dst)
{
    long long o = (long long)blockIdx.x * 256 + threadIdx.x;
    int d = (int)(o & 63);
    int h = (int)((o >> 6) & 15);
    int n = (int)((o >> 10) & 4095);
    int b = (int)(o >> 22);
    long long s = (((long long)(b * 16 + h)) * 4096 + n) * 64 + d;
    float v = src[s];
    float r = 0.f;
    #pragma unroll
    for (int tt = 0; tt < 13; tt++) {
        int nn = n + tt - 6;
        if (nn >= 0 && nn < 4096)
            r += w[h * 13 + tt] * src[s + (long long)(tt - 6) * 64];
    }
    dst[o] = rndtf(v + r);
}

// ---------------- launch ----------------------------------------------------
static constexpr int SMEM1 = (2 * 4608 + 2 * 2304) * 4;  // 55296 (tgemm)

extern "C" void kernel_launch(void* const* d_in, const int* in_sizes, int n_in,
                              void* d_out, int out_size)
{
    (void)in_sizes; (void)n_in; (void)out_size;
    const float* x      = (const float*)d_in[0];
    const float* w_qkv  = (const float*)d_in[1];
    const float* w_conv = (const float*)d_in[2];
    const float* w_fc   = (const float*)d_in[3];
    const float* b_fc   = (const float*)d_in[4];
    float* dout = (float*)d_out;

    void* vp_;
    #define SYMP(nm) float* nm##_p; cudaGetSymbolAddress(&vp_, nm); nm##_p = (float*)vp_;
    SYMP(g_xr)   SYMP(g_wqkvr) SYMP(g_wfcr)
    SYMP(g_Q)    SYMP(g_K)    SYMP(g_V)
    SYMP(g_ql)   SYMP(g_kl)
    SYMP(g_attn1) SYMP(g_attn2)
    SYMP(g_z0)   SYMP(g_z1)   SYMP(g_az)   SYMP(g_t2) SYMP(g_t4)
    SYMP(g_a3v)  SYMP(g_tmp2)
    SYMP(g_out)  SYMP(g_outT)
    #undef SYMP

    cudaFuncSetAttribute(tgemm3<false,false,false,true ,true >,
                         cudaFuncAttributeMaxDynamicSharedMemorySize, SMEM3);
    cudaFuncSetAttribute(tgemm3<true ,false,false,false,false>,
                         cudaFuncAttributeMaxDynamicSharedMemorySize, SMEM3);
    cudaFuncSetAttribute(tgemm3<false,false,false,false,true >,
                         cudaFuncAttributeMaxDynamicSharedMemorySize, SMEM3);
    cudaFuncSetAttribute(tgemm3<false,true ,false,false,true >,
                         cudaFuncAttributeMaxDynamicSharedMemorySize, SMEM3);
    cudaFuncSetAttribute(tgemm3<false,false,true ,false,false>,
                         cudaFuncAttributeMaxDynamicSharedMemorySize, SMEM3);
    cudaFuncSetAttribute(tgemm,
                         cudaFuncAttributeMaxDynamicSharedMemorySize, SMEM1);
    cudaFuncSetAttribute(sim1s,
                         cudaFuncAttributeMaxDynamicSharedMemorySize, SMEMS);
    cudaFuncSetAttribute(attn3v,
                         cudaFuncAttributeMaxDynamicSharedMemorySize, SMEMA);

    // 0. pre-round external GEMM inputs to tf32
    round_kernel<<<16384, 256>>>(x, g_xr_p, 4194304);
    round_kernel<<<3072, 256>>>(w_qkv, g_wqkvr_p, 786432);
    round_kernel<<<1024, 256>>>(w_fc, g_wfcr_p, 262144);

    // 1. qkv projection fused with split+scale+round -> g_Q/g_K/g_V
    tgemm3<false,false,false,true,true><<<dim3(24, 128, 1), 128, SMEM3>>>(
        g_xr_p, g_wqkvr_p, nullptr, nullptr, 1024, 1024, 3072, 0, 0, 0, 0,
        0.f, 1.f, nullptr, g_Q_p, g_K_p, g_V_p);

    // 2. landmarks (rounded)
    landmarks_kernel<<<4096, 256>>>(g_Q_p, g_K_p, g_ql_p, g_kl_p);

    // 3. attn1 = softmax(Q @ kl^T)  — fused producer+softmax
    sim1s<<<dim3(64, 64), 256, SMEMS>>>(g_Q_p, g_kl_p, g_attn1_p);

    // 4. a3v = softmax(ql @ K^T) @ V — flash-fused, attn3 never materialized
    attn3v<<<dim3(2, 64), 256, SMEMA>>>(g_ql_p, g_K_p, g_V_p, g_a3v_p);

    // 5. sim2 = ql @ kl^T  [256,64]@[256,64]^T
    tgemm3<true,false,false,false,false><<<dim3(2, 2, 64), 128, SMEM3>>>(
        g_ql_p, g_kl_p, g_attn2_p, nullptr, 64, 64, 64, 256,
        16384LL, 16384LL, 65536LL, 0.f, 1.f, nullptr, nullptr, nullptr, nullptr);

    // 6. softmax attn2 (in place, rounded)
    softmax256_kernel<<<2048, 256>>>(g_attn2_p, 16384);

    // 7. MP init
    mp_reset_kernel<<<1, 1>>>();
    mp_reduce_kernel<<<64, 256>>>(g_attn2_p);
    mp_init_kernel<<<16384, 256>>>(g_attn2_p, g_z0_p);

    // 8. 6 Newton-Schulz iterations, epilogue-fused form
    float* zin = g_z0_p; float* zout = g_z1_p;
    for (int it = 0; it < 6; it++) {
        tgemm3<false,false,false,false,true><<<dim3(2, 2, 64), 128, SMEM3>>>(
            g_attn2_p, zin, g_az_p, nullptr, 256, 256, 256, 256,
            65536LL, 65536LL, 65536LL, 0.f, 1.f, nullptr, nullptr, nullptr, nullptr);
        tgemm3<false,true,false,false,true><<<dim3(2, 2, 64), 128, SMEM3>>>(
            g_az_p, g_az_p, g_t2_p, g_az_p, 256, 256, 256, 256,
            65536LL, 65536LL, 65536LL, 7.f, 1.f, nullptr, nullptr, nullptr, nullptr);
        tgemm3<false,true,false,false,true><<<dim3(2, 2, 64), 128, SMEM3>>>(
            g_az_p, g_t2_p, g_t4_p, g_az_p, 256, 256, 256, 256,
            65536LL, 65536LL, 65536LL, 15.f, 1.f, nullptr, nullptr, nullptr, nullptr);
        tgemm3<false,true,false,false,true><<<dim3(2, 2, 64), 128, SMEM3>>>(
            zin, g_t4_p, zout, zin, 256, 256, 256, 256,
            65536LL, 65536LL, 65536LL, 13.f, 0.25f, nullptr, nullptr, nullptr, nullptr);
        float* tmp = zin; zin = zout; zout = tmp;
    }

    // 9. tmp2 = z @ a3v   [256,256]@[256,64]
    tgemm<<<dim3(1, 2, 64), 256, SMEM1>>>(
        zin, g_a3v_p, g_tmp2_p, 256, 256, 64, 64,
        65536LL, 16384LL, 16384LL);

    // 10. out = attn1 @ tmp2   [4096,256]@[256,64]
    tgemm<<<dim3(1, 32, 64), 256, SMEM1>>>(
        g_attn1_p, g_tmp2_p, g_out_p, 256, 256, 64, 64,
        1048576LL, 16384LL, 262144LL);

    // 11. fused depthwise conv residual + transpose to [b,n,inner] (rounded)
    conv_tr_kernel<<<65536, 256>>>(g_out_p, w_conv, g_outT_p);

    // 12. final fc: d_out = outT @ w_fc + b_fc   [16384,1024]@[1024,1024]
    tgemm3<false,false,true,false,false><<<dim3(8, 128, 1), 128, SMEM3>>>(
        g_outT_p, g_wfcr_p, dout, nullptr, 1024, 1024, 1024, 1024,
        0, 0, 0, 0.f, 1.f, b_fc, nullptr, nullptr, nullptr);
}

// round 15
// speedup vs baseline: 1.0881x; 1.0881x over previous
#include <cuda_runtime.h>
#include <cstdint>

// ============================================================================
// NystromAttention — tf32 tensor cores (R13 kernels, unchanged) + graph-level
// parallelism: the MP chain and the attn chains run on forked streams and are
// captured as parallel branches of the CUDA graph.
// ============================================================================

// ---------------- scratch (device globals) ----------------------------------
__device__ float g_xr   [16777216];
__device__ float g_wqkvr[3145728];
__device__ float g_wfcr [1048576];
__device__ float g_Q    [16777216];  // [b,h,n,d] scaled, rounded
__device__ float g_K    [16777216];
__device__ float g_V    [16777216];
__device__ float g_ql   [1048576];   // [bh, 256, 64]
__device__ float g_kl   [1048576];
__device__ float g_attn1[67108864];  // [bh, 4096, 256] (softmaxed)
__device__ float g_attn3[67108864];  // [bh, 256, 4096]
__device__ float g_attn2[4194304];   // [bh, 256, 256]
__device__ float g_z0   [4194304];
__device__ float g_z1   [4194304];
__device__ float g_az   [4194304];
__device__ float g_t2   [4194304];
__device__ float g_t4   [4194304];
__device__ float g_a3v  [1048576];   // [bh, 256, 64]
__device__ float g_tmp2 [1048576];   // [bh, 256, 64]
__device__ float g_out  [16777216];  // [b,h,n,d]
__device__ float g_outT [16777216];  // [b,n,1024]
__device__ unsigned int g_m1, g_m2;

__device__ __forceinline__ unsigned f2tf(float f) {
    unsigned u;
    asm("cvt.rna.tf32.f32 %0, %1;" : "=r"(u) : "f"(f));
    return u;
}
__device__ __forceinline__ float rndtf(float f) {
    return __uint_as_float(f2tf(f));
}
__device__ __forceinline__ void cp16(unsigned d, const void* s) {
    asm volatile("cp.async.cg.shared.global [%0], [%1], 16;"
                 :: "r"(d), "l"(s) : "memory");
}
#define CP_COMMIT() asm volatile("cp.async.commit_group;" ::: "memory")
#define CP_WAIT0()  asm volatile("cp.async.wait_group 0;" ::: "memory")
#define CP_WAIT1()  asm volatile("cp.async.wait_group 1;" ::: "memory")

#define MMA_TF32(acc, a0,a1,a2,a3, b0,b1)                                     \
    asm volatile(                                                             \
        "mma.sync.aligned.m16n8k8.row.col.f32.tf32.tf32.f32 "                 \
        "{%0,%1,%2,%3}, {%4,%5,%6,%7}, {%8,%9}, {%0,%1,%2,%3};"               \
        : "+f"(acc[0]), "+f"(acc[1]), "+f"(acc[2]), "+f"(acc[3])              \
        : "r"(a0), "r"(a1), "r"(a2), "r"(a3), "r"(b0), "r"(b1))

// ============================================================================
// tgemm3 (exact R8): CTA 128x128x32, 4 warps (2x2), warp 64x64, 2-stage
// cp.async double buffer. Inputs MUST be tf32-pre-rounded fp32.
// ============================================================================
static constexpr int AW = 128 * 36;
static constexpr int BW_NN = 32 * 136;
static constexpr int BW_NT = 128 * 36;
static constexpr int SMEM3 = (2 * AW + 2 * BW_NT) * 4;  // 73728

template<bool TRANSB, bool EPI, bool BIAS, bool QKVE, bool RND>
__global__ __launch_bounds__(128)
void tgemm3(const float* __restrict__ A, const float* __restrict__ B,
            float* __restrict__ C, const float* __restrict__ E,
            int Kdim, int lda, int ldb, int ldc,
            long long sA, long long sB, long long sC,
            float alpha, float outScale, const float* __restrict__ bias,
            float* __restrict__ qp, float* __restrict__ kp,
            float* __restrict__ vp)
{
    constexpr int BW = TRANSB ? BW_NT : BW_NN;
    extern __shared__ unsigned sh[];
    unsigned* Ash = sh;
    unsigned* Bsh = sh + 2 * AW;

    const float* Ab = A + (long long)blockIdx.z * sA;
    const float* Bb = B + (long long)blockIdx.z * sB;
    float*       Cb = C + (long long)blockIdx.z * sC;
    const float* Eb = EPI ? (E + (long long)blockIdx.z * sC) : nullptr;

    const int row0 = blockIdx.y * 128;
    const int col0 = blockIdx.x * 128;
    const int t    = threadIdx.x;
    const int lane = t & 31;
    const int w    = t >> 5;
    const int wm   = w & 1;
    const int wn   = w >> 1;
    const int g    = lane >> 2;
    const int tg   = lane & 3;

    const unsigned aBase = (unsigned)__cvta_generic_to_shared(Ash);
    const unsigned bBase = (unsigned)__cvta_generic_to_shared(Bsh);

    auto issue = [&](int k0, int st) {
        unsigned ab = aBase + st * (AW * 4);
        #pragma unroll
        for (int l = 0; l < 8; l++) {
            int c  = t + l * 128;
            int r  = c >> 3;
            int kq = (c & 7) << 2;
            cp16(ab + (unsigned)(r * 36 + kq) * 4,
                 Ab + (long long)(row0 + r) * lda + k0 + kq);
        }
        unsigned bb = bBase + st * (BW * 4);
        #pragma unroll
        for (int l = 0; l < 8; l++) {
            int c = t + l * 128;
            if (!TRANSB) {
                int k  = c >> 5;
                int n4 = (c & 31) << 2;
                cp16(bb + (unsigned)(k * 136 + n4) * 4,
                     Bb + (long long)(k0 + k) * ldb + col0 + n4);
            } else {
                int j  = c >> 3;
                int kq = (c & 7) << 2;
                cp16(bb + (unsigned)(j * 36 + kq) * 4,
                     Bb + (long long)(col0 + j) * ldb + k0 + kq);
            }
        }
        CP_COMMIT();
    };

    float acc[4][8][4];
    #pragma unroll
    for (int mi = 0; mi < 4; mi++)
        #pragma unroll
        for (int ni = 0; ni < 8; ni++)
            #pragma unroll
            for (int q = 0; q < 4; q++) acc[mi][ni][q] = 0.f;

    issue(0, 0);

    int si = 0;
    for (int k0 = 0; k0 < Kdim; k0 += 32) {
        bool more = (k0 + 32 < Kdim);
        if (more) { issue(k0 + 32, si ^ 1); CP_WAIT1(); }
        else      { CP_WAIT0(); }
        __syncthreads();

        const unsigned* Ap = Ash + si * AW;
        const unsigned* Bp = Bsh + si * BW;
        #pragma unroll
        for (int ks = 0; ks < 4; ks++) {
            const int kk = ks * 8;
            unsigned af[4][4], bf[8][2];
            #pragma unroll
            for (int mi = 0; mi < 4; mi++) {
                int rb = wm * 64 + mi * 16;
                af[mi][0] = Ap[(rb + g    ) * 36 + kk + tg];
                af[mi][1] = Ap[(rb + 8 + g) * 36 + kk + tg];
                af[mi][2] = Ap[(rb + g    ) * 36 + kk + 4 + tg];
                af[mi][3] = Ap[(rb + 8 + g) * 36 + kk + 4 + tg];
            }
            #pragma unroll
            for (int ni = 0; ni < 8; ni++) {
                int cb = wn * 64 + ni * 8;
                if (TRANSB) {
                    bf[ni][0] = Bp[(cb + g) * 36 + kk + tg];
                    bf[ni][1] = Bp[(cb + g) * 36 + kk + 4 + tg];
                } else {
                    bf[ni][0] = Bp[(kk + tg) * 136 + cb + g];
                    bf[ni][1] = Bp[(kk + 4 + tg) * 136 + cb + g];
                }
            }
            #pragma unroll
            for (int mi = 0; mi < 4; mi++)
                #pragma unroll
                for (int ni = 0; ni < 8; ni++)
                    MMA_TF32(acc[mi][ni],
                             af[mi][0], af[mi][1], af[mi][2], af[mi][3],
                             bf[ni][0], bf[ni][1]);
        }
        __syncthreads();
        si ^= 1;
    }

    #pragma unroll
    for (int mi = 0; mi < 4; mi++) {
        int r = row0 + wm * 64 + mi * 16 + g;
        #pragma unroll
        for (int ni = 0; ni < 8; ni++) {
            int c = col0 + wn * 64 + ni * 8 + 2 * tg;
            float v00 = acc[mi][ni][0], v01 = acc[mi][ni][1];
            float v10 = acc[mi][ni][2], v11 = acc[mi][ni][3];
            if (QKVE) {
                int which = c >> 10, hh = (c >> 6) & 15, d = c & 63;
                float sc = (which == 0) ? 0.125f : 1.f;
                float* dst = (which == 0) ? qp : ((which == 1) ? kp : vp);
                long long base =
                    (((long long)((r >> 12) * 16 + hh)) * 4096 + (r & 4095)) * 64 + d;
                *reinterpret_cast<float2*>(dst + base) =
                    make_float2(rndtf(v00 * sc), rndtf(v01 * sc));
                *reinterpret_cast<float2*>(dst + base + 512) =
                    make_float2(rndtf(v10 * sc), rndtf(v11 * sc));
                continue;
            }
            if (EPI) {
                float2 e0 = *reinterpret_cast<const float2*>(
                    Eb + (long long)r * ldc + c);
                float2 e1 = *reinterpret_cast<const float2*>(
                    Eb + (long long)(r + 8) * ldc + c);
                v00 = (alpha * e0.x - v00) * outScale;
                v01 = (alpha * e0.y - v01) * outScale;
                v10 = (alpha * e1.x - v10) * outScale;
                v11 = (alpha * e1.y - v11) * outScale;
            } else {
                float b0 = 0.f, b1 = 0.f;
                if (BIAS) { b0 = bias[c]; b1 = bias[c + 1]; }
                v00 = v00 * outScale + b0;  v01 = v01 * outScale + b1;
                v10 = v10 * outScale + b0;  v11 = v11 * outScale + b1;
            }
            if (RND) {
                v00 = rndtf(v00); v01 = rndtf(v01);
                v10 = rndtf(v10); v11 = rndtf(v11);
            }
            *reinterpret_cast<float2*>(Cb + (long long)r * ldc + c) =
                make_float2(v00, v01);
            *reinterpret_cast<float2*>(Cb + (long long)(r + 8) * ldc + c) =
                make_float2(v10, v11);
        }
    }
}

// ============================================================================
// sim1s (exact R13): attn1 = softmax(Q @ kl^T), 64 full rows per CTA
// ============================================================================
static constexpr int S_AW = 2 * 64 * 36;
static constexpr int S_BW = 2 * 256 * 36;
static constexpr int SMEMS = (S_AW + S_BW) * 4;   // 92160

__global__ __launch_bounds__(256, 2)
void sim1s(const float* __restrict__ Q, const float* __restrict__ KL,
           float* __restrict__ OUT)
{
    extern __shared__ unsigned sh[];
    unsigned* Ash = sh;
    unsigned* Bsh = sh + S_AW;
    unsigned* Ss  = Bsh;

    const int bh   = blockIdx.y;
    const int row0 = blockIdx.x * 64;
    const int t    = threadIdx.x;
    const int lane = t & 31;
    const int w    = t >> 5;
    const int wm   = w & 1;
    const int wn   = w >> 1;
    const int g    = lane >> 2;
    const int tg   = lane & 3;

    const float* Qb  = Q  + (long long)bh * 262144 + (long long)row0 * 64;
    const float* KLb = KL + (long long)bh * 16384;
    float*       Ob  = OUT + (long long)bh * 1048576 + (long long)row0 * 256;

    const unsigned aBase = (unsigned)__cvta_generic_to_shared(Ash);
    const unsigned bBase = (unsigned)__cvta_generic_to_shared(Bsh);

    #pragma unroll
    for (int l = 0; l < 4; l++) {
        int idx = t + l * 256;
        int r  = idx >> 4;
        int k0 = (idx & 15) << 2;
        cp16(aBase + (unsigned)((k0 >> 5) * 2304 + r * 36 + (k0 & 31)) * 4,
             Qb + r * 64 + k0);
    }
    #pragma unroll
    for (int l = 0; l < 16; l++) {
        int idx = t + l * 256;
        int n  = idx >> 4;
        int k0 = (idx & 15) << 2;
        cp16(bBase + (unsigned)((k0 >> 5) * 9216 + n * 36 + (k0 & 31)) * 4,
             KLb + n * 64 + k0);
    }
    CP_COMMIT();
    CP_WAIT0();
    __syncthreads();

    float acc[2][8][4];
    #pragma unroll
    for (int mi = 0; mi < 2; mi++)
        #pragma unroll
        for (int ni = 0; ni < 8; ni++)
            #pragma unroll
            for (int q = 0; q < 4; q++) acc[mi][ni][q] = 0.f;

    #pragma unroll
    for (int ch = 0; ch < 2; ch++) {
        const unsigned* Ap = Ash + ch * 2304;
        const unsigned* Bp = Bsh + ch * 9216;
        #pragma unroll
        for (int ks = 0; ks < 4; ks++) {
            const int kk = ks * 8;
            unsigned af[2][4], bf[8][2];
            #pragma unroll
            for (int mi = 0; mi < 2; mi++) {
                int rb = wm * 32 + mi * 16;
                af[mi][0] = Ap[(rb + g    ) * 36 + kk + tg];
                af[mi][1] = Ap[(rb + 8 + g) * 36 + kk + tg];
                af[mi][2] = Ap[(rb + g    ) * 36 + kk + 4 + tg];
                af[mi][3] = Ap[(rb + 8 + g) * 36 + kk + 4 + tg];
            }
            #pragma unroll
            for (int ni = 0; ni < 8; ni++) {
                int cb = wn * 64 + ni * 8;
                bf[ni][0] = Bp[(cb + g) * 36 + kk + tg];
                bf[ni][1] = Bp[(cb + g) * 36 + kk + 4 + tg];
            }
            #pragma unroll
            for (int mi = 0; mi < 2; mi++)
                #pragma unroll
                for (int ni = 0; ni < 8; ni++)
                    MMA_TF32(acc[mi][ni],
                             af[mi][0], af[mi][1], af[mi][2], af[mi][3],
                             bf[ni][0], bf[ni][1]);
        }
    }
    __syncthreads();

    #pragma unroll
    for (int mi = 0; mi < 2; mi++) {
        int r = wm * 32 + mi * 16 + g;
        #pragma unroll
        for (int ni = 0; ni < 8; ni++) {
            int c = wn * 64 + ni * 8 + 2 * tg;
            unsigned* p0 = Ss + r * 260 + c;
            p0[0] = __float_as_uint(acc[mi][ni][0]);
            p0[1] = __float_as_uint(acc[mi][ni][1]);
            unsigned* p1 = Ss + (r + 8) * 260 + c;
            p1[0] = __float_as_uint(acc[mi][ni][2]);
            p1[1] = __float_as_uint(acc[mi][ni][3]);
        }
    }
    __syncthreads();

    #pragma unroll
    for (int rr = 0; rr < 8; rr++) {
        int r = w * 8 + rr;
        float v[8];
        float mx = -1e30f;
        #pragma unroll
        for (int i = 0; i < 8; i++) {
            v[i] = __uint_as_float(Ss[r * 260 + lane + 32 * i]);
            mx = fmaxf(mx, v[i]);
        }
        #pragma unroll
        for (int o = 16; o > 0; o >>= 1)
            mx = fmaxf(mx, __shfl_xor_sync(0xffffffffu, mx, o));
        float s = 0.f;
        #pragma unroll
        for (int i = 0; i < 8; i++) { v[i] = expf(v[i] - mx); s += v[i]; }
        #pragma unroll
        for (int o = 16; o > 0; o >>= 1)
            s += __shfl_xor_sync(0xffffffffu, s, o);
        float inv = 1.f / s;
        #pragma unroll
        for (int i = 0; i < 8; i++)
            Ob[r * 256 + lane + 32 * i] = rndtf(v[i] * inv);
    }
}

// ============================================================================
// tgemm: CTA 128x64x32, 8 warps (4x2), warp 32x32 — N=64 tails
// SPLITK: grid.z = bh*8+ks; atomicAdd epilogue (C pre-zeroed)
// ============================================================================
template<bool SPLITK>
__global__ __launch_bounds__(256)
void tgemm(const float* __restrict__ A, const float* __restrict__ B,
           float* __restrict__ C, int Kdim, int lda, int ldb, int ldc,
           long long sA, long long sB, long long sC)
{
    extern __shared__ unsigned sh[];
    unsigned* As = sh;
    unsigned* Bs = sh + 2 * 4608;

    const float* Ab;
    const float* Bb;
    float*       Cb;
    if (SPLITK) {
        int bh = blockIdx.z >> 3, ks = blockIdx.z & 7;
        Ab = A + (long long)bh * sA + (long long)ks * Kdim;
        Bb = B + (long long)bh * sB + (long long)ks * Kdim * ldb;
        Cb = C + (long long)bh * sC;
    } else {
        Ab = A + (long long)blockIdx.z * sA;
        Bb = B + (long long)blockIdx.z * sB;
        Cb = C + (long long)blockIdx.z * sC;
    }

    const int row0 = blockIdx.y * 128;
    const int col0 = blockIdx.x * 64;
    const int t    = threadIdx.x;
    const int lane = t & 31;
    const int w    = t >> 5;
    const int wm   = w & 3;
    const int wn   = w >> 2;
    const int g    = lane >> 2;
    const int tg   = lane & 3;

    float4 aR[4];
    float4 bR[2];

    auto ldA = [&](int k0) {
        #pragma unroll
        for (int l = 0; l < 4; l++) {
            int idx = t + l * 256;
            int r   = idx >> 3;
            int kq  = (idx & 7) << 2;
            aR[l] = *reinterpret_cast<const float4*>(
                Ab + (long long)(row0 + r) * lda + k0 + kq);
        }
    };
    auto stA = [&](int st) {
        unsigned* Ap = As + st * 4608;
        #pragma unroll
        for (int l = 0; l < 4; l++) {
            int idx = t + l * 256;
            int r   = idx >> 3;
            int kq  = (idx & 7) << 2;
            uint4 u = make_uint4(f2tf(aR[l].x), f2tf(aR[l].y),
                                 f2tf(aR[l].z), f2tf(aR[l].w));
            *reinterpret_cast<uint4*>(Ap + r * 36 + kq) = u;
        }
    };
    auto ldB = [&](int k0) {
        #pragma unroll
        for (int l = 0; l < 2; l++) {
            int idx = t + l * 256;
            int r  = idx >> 4;
            int cq = (idx & 15) << 2;
            bR[l] = *reinterpret_cast<const float4*>(
                Bb + (long long)(k0 + r) * ldb + col0 + cq);
        }
    };
    auto stB = [&](int st) {
        unsigned* Bp = Bs + st * 2304;
        #pragma unroll
        for (int l = 0; l < 2; l++) {
            int idx = t + l * 256;
            int r  = idx >> 4;
            int cq = (idx & 15) << 2;
            uint4 u = make_uint4(f2tf(bR[l].x), f2tf(bR[l].y),
                                 f2tf(bR[l].z), f2tf(bR[l].w));
            *reinterpret_cast<uint4*>(Bp + r * 72 + cq) = u;
        }
    };

    float acc[2][4][4];
    #pragma unroll
    for (int mi = 0; mi < 2; mi++)
        #pragma unroll
        for (int ni = 0; ni < 4; ni++)
            #pragma unroll
            for (int q = 0; q < 4; q++) acc[mi][ni][q] = 0.f;

    ldA(0); ldB(0);
    stA(0); stB(0);
    __syncthreads();

    int s = 0;
    for (int k0 = 0; k0 < Kdim; k0 += 32) {
        bool more = (k0 + 32 < Kdim);
        if (more) { ldA(k0 + 32); ldB(k0 + 32); }

        const unsigned* Ap = As + s * 4608;
        const unsigned* Bp = Bs + s * 2304;
        #pragma unroll
        for (int ks = 0; ks < 4; ks++) {
            const int kk = ks * 8;
            unsigned af[2][4], bf[4][2];
            #pragma unroll
            for (int mi = 0; mi < 2; mi++) {
                int rb = wm * 32 + mi * 16;
                af[mi][0] = Ap[(rb + g    ) * 36 + kk + tg];
                af[mi][1] = Ap[(rb + 8 + g) * 36 + kk + tg];
                af[mi][2] = Ap[(rb + g    ) * 36 + kk + 4 + tg];
                af[mi][3] = Ap[(rb + 8 + g) * 36 + kk + 4 + tg];
            }
            #pragma unroll
            for (int ni = 0; ni < 4; ni++) {
                int cb = wn * 32 + ni * 8;
                bf[ni][0] = Bp[(kk + tg) * 72 + cb + g];
                bf[ni][1] = Bp[(kk + 4 + tg) * 72 + cb + g];
            }
            #pragma unroll
            for (int mi = 0; mi < 2; mi++)
                #pragma unroll
                for (int ni = 0; ni < 4; ni++)
                    MMA_TF32(acc[mi][ni],
                             af[mi][0], af[mi][1], af[mi][2], af[mi][3],
                             bf[ni][0], bf[ni][1]);
        }

        if (more) {
            stA(s ^ 1); stB(s ^ 1);
            __syncthreads();
        }
        s ^= 1;
    }

    #pragma unroll
    for (int mi = 0; mi < 2; mi++) {
        int r = row0 + wm * 32 + mi * 16 + g;
        #pragma unroll
        for (int ni = 0; ni < 4; ni++) {
            int c = col0 + wn * 32 + ni * 8 + 2 * tg;
            if (SPLITK) {
                float* p0 = Cb + (long long)r * ldc + c;
                atomicAdd(p0,                          acc[mi][ni][0]);
                atomicAdd(p0 + 1,                      acc[mi][ni][1]);
                atomicAdd(p0 + (long long)8 * ldc,     acc[mi][ni][2]);
                atomicAdd(p0 + (long long)8 * ldc + 1, acc[mi][ni][3]);
            } else {
                *reinterpret_cast<float2*>(Cb + (long long)r * ldc + c) =
                    make_float2(acc[mi][ni][0], acc[mi][ni][1]);
                *reinterpret_cast<float2*>(Cb + (long long)(r + 8) * ldc + c) =
                    make_float2(acc[mi][ni][2], acc[mi][ni][3]);
            }
        }
    }
}

// ---------------- elementwise / reductions ---------------------------------
__global__ void round_kernel(const float* __restrict__ src,
                             float* __restrict__ dst, int n4)
{
    int i = blockIdx.x * 256 + threadIdx.x;
    if (i >= n4) return;
    float4 v = reinterpret_cast<const float4*>(src)[i];
    v.x = rndtf(v.x); v.y = rndtf(v.y); v.z = rndtf(v.z); v.w = rndtf(v.w);
    reinterpret_cast<float4*>(dst)[i] = v;
}

__global__ void landmarks_kernel(const float* __restrict__ Q,
                                 const float* __restrict__ K,
                                 float* __restrict__ ql, float* __restrict__ kl)
{
    int i = blockIdx.x * 256 + threadIdx.x;
    int d = i & 63;
    int m = (i >> 6) & 255;
    int bh = i >> 14;
    long long base = ((long long)bh * 4096 + m * 16) * 64 + d;
    float sq = 0.f, sk = 0.f;
    #pragma unroll
    for (int j = 0; j < 16; j++) {
        sq += Q[base + j * 64];
        sk += K[base + j * 64];
    }
    ql[i] = rndtf(sq * 0.0625f);
    kl[i] = rndtf(sk * 0.0625f);
}

__global__ void softmax256_kernel(float* __restrict__ data, int rows)
{
    int gw   = (int)((blockIdx.x * (long long)blockDim.x + threadIdx.x) >> 5);
    int lane = threadIdx.x & 31;
    if (gw >= rows) return;
    float* p = data + (long long)gw * 256;
    float v[8];
    float mx = -1e30f;
    #pragma unroll
    for (int i = 0; i < 8; i++) { v[i] = p[lane + 32 * i]; mx = fmaxf(mx, v[i]); }
    #pragma unroll
    for (int o = 16; o > 0; o >>= 1) mx = fmaxf(mx, __shfl_xor_sync(0xffffffffu, mx, o));
    float s = 0.f;
    #pragma unroll
    for (int i = 0; i < 8; i++) { v[i] = expf(v[i] - mx); s += v[i]; }
    #pragma unroll
    for (int o = 16; o > 0; o >>= 1) s += __shfl_xor_sync(0xffffffffu, s, o);
    float inv = 1.f / s;
    #pragma unroll
    for (int i = 0; i < 8; i++) p[lane + 32 * i] = rndtf(v[i] * inv);
}

__global__ void softmax4096_kernel(float* __restrict__ data)
{
    float* p = data + (long long)blockIdx.x * 4096;
    int t = threadIdx.x;
    float v[16];
    float mx = -1e30f;
    #pragma unroll
    for (int i = 0; i < 16; i++) { v[i] = p[t + 256 * i]; mx = fmaxf(mx, v[i]); }
    __shared__ float red[256];
    red[t] = mx; __syncthreads();
    for (int s = 128; s > 0; s >>= 1) {
        if (t < s) red[t] = fmaxf(red[t], red[t + s]);
        __syncthreads();
    }
    mx = red[0]; __syncthreads();
    float sum = 0.f;
    #pragma unroll
    for (int i = 0; i < 16; i++) { v[i] = expf(v[i] - mx); sum += v[i]; }
    red[t] = sum; __syncthreads();
    for (int s = 128; s > 0; s >>= 1) {
        if (t < s) red[t] += red[t + s];
        __syncthreads();
    }
    float inv = 1.f / red[0];
    #pragma unroll
    for (int i = 0; i < 16; i++) p[t + 256 * i] = rndtf(v[i] * inv);
}

__global__ void mp_reset_kernel() { g_m1 = 0u; g_m2 = 0u; }

__global__ void mp_reduce_kernel(const float* __restrict__ a)
{
    int bh = blockIdx.x;
    int j  = threadIdx.x;
    const float* p = a + (long long)bh * 65536;
    float rs = 0.f, cs = 0.f;
    for (int i = 0; i < 256; i++) {
        rs += fabsf(p[j * 256 + i]);
        cs += fabsf(p[i * 256 + j]);
    }
    __shared__ float r1[256], r2[256];
    r1[j] = rs; r2[j] = cs; __syncthreads();
    for (int s = 128; s > 0; s >>= 1) {
        if (j < s) { r1[j] = fmaxf(r1[j], r1[j + s]); r2[j] = fmaxf(r2[j], r2[j + s]); }
        __syncthreads();
    }
    if (j == 0) {
        atomicMax(&g_m1, __float_as_uint(r1[0]));
        atomicMax(&g_m2, __float_as_uint(r2[0]));
    }
}

__global__ void mp_init_kernel(const float* __restrict__ a, float* __restrict__ z)
{
    long long i = (long long)blockIdx.x * 256 + threadIdx.x;
    int col = (int)(i & 255);
    int row = (int)((i >> 8) & 255);
    long long bh = i >> 16;
    float denom = __uint_as_float(g_m1) * __uint_as_float(g_m2);
    z[i] = rndtf(a[bh * 65536 + (long long)col * 256 + row] / denom);
}

// fused: depthwise residual conv (K=13, pad 6) + [b,h,n,d] -> [b,n,h*64+d]
__global__ void conv_tr_kernel(const float* __restrict__ src,
                               const float* __restrict__ w,
                               float* __restrict__ dst)
{
    long long o = (long long)blockIdx.x * 256 + threadIdx.x;
    int d = (int)(o & 63);
    int h = (int)((o >> 6) & 15);
    int n = (int)((o >> 10) & 4095);
    int b = (int)(o >> 22);
    long long s = (((long long)(b * 16 + h)) * 4096 + n) * 64 + d;
    float v = src[s];
    float r = 0.f;
    #pragma unroll
    for (int tt = 0; tt < 13; tt++) {
        int nn = n + tt - 6;
        if (nn >= 0 && nn < 4096)
            r += w[h * 13 + tt] * src[s + (long long)(tt - 6) * 64];
    }
    dst[o] = rndtf(v + r);
}

// ---------------- launch ----------------------------------------------------
static constexpr int SMEM1 = (2 * 4608 + 2 * 2304) * 4;  // 55296 (tgemm)

extern "C" void kernel_launch(void* const* d_in, const int* in_sizes, int n_in,
                              void* d_out, int out_size)
{
    (void)in_sizes; (void)n_in; (void)out_size;
    const float* x      = (const float*)d_in[0];
    const float* w_qkv  = (const float*)d_in[1];
    const float* w_conv = (const float*)d_in[2];
    const float* w_fc   = (const float*)d_in[3];
    const float* b_fc   = (const float*)d_in[4];
    float* dout = (float*)d_out;

    void* vp_;
    #define SYMP(nm) float* nm##_p; cudaGetSymbolAddress(&vp_, nm); nm##_p = (float*)vp_;
    SYMP(g_xr)   SYMP(g_wqkvr) SYMP(g_wfcr)
    SYMP(g_Q)    SYMP(g_K)    SYMP(g_V)
    SYMP(g_ql)   SYMP(g_kl)
    SYMP(g_attn1) SYMP(g_attn3) SYMP(g_attn2)
    SYMP(g_z0)   SYMP(g_z1)   SYMP(g_az)   SYMP(g_t2) SYMP(g_t4)
    SYMP(g_a3v)  SYMP(g_tmp2)
    SYMP(g_out)  SYMP(g_outT)
    #undef SYMP

    cudaFuncSetAttribute(tgemm3<false,false,false,true ,true >,
                         cudaFuncAttributeMaxDynamicSharedMemorySize, SMEM3);
    cudaFuncSetAttribute(tgemm3<true ,false,false,false,false>,
                         cudaFuncAttributeMaxDynamicSharedMemorySize, SMEM3);
    cudaFuncSetAttribute(tgemm3<false,false,false,false,true >,
                         cudaFuncAttributeMaxDynamicSharedMemorySize, SMEM3);
    cudaFuncSetAttribute(tgemm3<false,true ,false,false,true >,
                         cudaFuncAttributeMaxDynamicSharedMemorySize, SMEM3);
    cudaFuncSetAttribute(tgemm3<false,false,true ,false,false>,
                         cudaFuncAttributeMaxDynamicSharedMemorySize, SMEM3);
    cudaFuncSetAttribute(tgemm<false>,
                         cudaFuncAttributeMaxDynamicSharedMemorySize, SMEM1);
    cudaFuncSetAttribute(tgemm<true>,
                         cudaFuncAttributeMaxDynamicSharedMemorySize, SMEM1);
    cudaFuncSetAttribute(sim1s,
                         cudaFuncAttributeMaxDynamicSharedMemorySize, SMEMS);

    // Lazily-created side stream + fork/join events (created on the first,
    // non-captured correctness call; reused identically on every call).
    static cudaStream_t s1 = nullptr;
    static cudaEvent_t evF = nullptr, evJ = nullptr;
    if (s1 == nullptr) {
        cudaStreamCreateWithFlags(&s1, cudaStreamNonBlocking);
        cudaEventCreateWithFlags(&evF, cudaEventDisableTiming);
        cudaEventCreateWithFlags(&evJ, cudaEventDisableTiming);
    }

    // 0. pre-round external GEMM inputs to tf32
    round_kernel<<<16384, 256>>>(x, g_xr_p, 4194304);
    round_kernel<<<3072, 256>>>(w_qkv, g_wqkvr_p, 786432);
    round_kernel<<<1024, 256>>>(w_fc, g_wfcr_p, 262144);

    // 1. qkv projection fused with split+scale+round -> g_Q/g_K/g_V
    tgemm3<false,false,false,true,true><<<dim3(24, 128, 1), 128, SMEM3>>>(
        g_xr_p, g_wqkvr_p, nullptr, nullptr, 1024, 1024, 3072, 0, 0, 0, 0,
        0.f, 1.f, nullptr, g_Q_p, g_K_p, g_V_p);

    // 2. landmarks (rounded)
    landmarks_kernel<<<4096, 256>>>(g_Q_p, g_K_p, g_ql_p, g_kl_p);

    // ---- fork: MP chain on s1, attn chains on default stream --------------
    cudaEventRecord(evF, 0);
    cudaStreamWaitEvent(s1, evF, 0);

    // [s1] sim2 = ql @ kl^T
    tgemm3<true,false,false,false,false><<<dim3(2, 2, 64), 128, SMEM3, s1>>>(
        g_ql_p, g_kl_p, g_attn2_p, nullptr, 64, 64, 64, 256,
        16384LL, 16384LL, 65536LL, 0.f, 1.f, nullptr, nullptr, nullptr, nullptr);
    // [s1] softmax attn2
    softmax256_kernel<<<2048, 256, 0, s1>>>(g_attn2_p, 16384);
    // [s1] MP init
    mp_reset_kernel<<<1, 1, 0, s1>>>();
    mp_reduce_kernel<<<64, 256, 0, s1>>>(g_attn2_p);
    mp_init_kernel<<<16384, 256, 0, s1>>>(g_attn2_p, g_z0_p);
    // [s1] 6 Newton-Schulz iterations, epilogue-fused form
    float* zin = g_z0_p; float* zout = g_z1_p;
    for (int it = 0; it < 6; it++) {
        tgemm3<false,false,false,false,true><<<dim3(2, 2, 64), 128, SMEM3, s1>>>(
            g_attn2_p, zin, g_az_p, nullptr, 256, 256, 256, 256,
            65536LL, 65536LL, 65536LL, 0.f, 1.f, nullptr, nullptr, nullptr, nullptr);
        tgemm3<false,true,false,false,true><<<dim3(2, 2, 64), 128, SMEM3, s1>>>(
            g_az_p, g_az_p, g_t2_p, g_az_p, 256, 256, 256, 256,
            65536LL, 65536LL, 65536LL, 7.f, 1.f, nullptr, nullptr, nullptr, nullptr);
        tgemm3<false,true,false,false,true><<<dim3(2, 2, 64), 128, SMEM3, s1>>>(
            g_az_p, g_t2_p, g_t4_p, g_az_p, 256, 256, 256, 256,
            65536LL, 65536LL, 65536LL, 15.f, 1.f, nullptr, nullptr, nullptr, nullptr);
        tgemm3<false,true,false,false,true><<<dim3(2, 2, 64), 128, SMEM3, s1>>>(
            zin, g_t4_p, zout, zin, 256, 256, 256, 256,
            65536LL, 65536LL, 65536LL, 13.f, 0.25f, nullptr, nullptr, nullptr, nullptr);
        float* tmp = zin; zin = zout; zout = tmp;
    }
    cudaEventRecord(evJ, s1);

    // [default] attn1 = softmax(Q @ kl^T)  — fused producer+softmax
    sim1s<<<dim3(64, 64), 256, SMEMS>>>(g_Q_p, g_kl_p, g_attn1_p);

    // [default] sim3 = ql @ K^T   [256,64]@[4096,64]^T
    tgemm3<true,false,false,false,false><<<dim3(32, 2, 64), 128, SMEM3>>>(
        g_ql_p, g_K_p, g_attn3_p, nullptr, 64, 64, 64, 4096,
        16384LL, 262144LL, 1048576LL, 0.f, 1.f, nullptr, nullptr, nullptr, nullptr);

    // [default] softmax attn3
    softmax4096_kernel<<<16384, 256>>>(g_attn3_p);

    // [default] a3v = attn3 @ V, split-K x8 atomic epilogue
    cudaMemsetAsync(g_a3v_p, 0, 1048576 * sizeof(float));
    tgemm<true><<<dim3(1, 2, 512), 256, SMEM1>>>(
        g_attn3_p, g_V_p, g_a3v_p, 512, 4096, 64, 64,
        1048576LL, 262144LL, 16384LL);

    // ---- join: default stream waits for MP chain --------------------------
    cudaStreamWaitEvent(0, evJ, 0);

    // 9. tmp2 = z @ a3v   [256,256]@[256,64]
    tgemm<false><<<dim3(1, 2, 64), 256, SMEM1>>>(
        zin, g_a3v_p, g_tmp2_p, 256, 256, 64, 64,
        65536LL, 16384LL, 16384LL);

    // 10. out = attn1 @ tmp2   [4096,256]@[256,64]
    tgemm<false><<<dim3(1, 32, 64), 256, SMEM1>>>(
        g_attn1_p, g_tmp2_p, g_out_p, 256, 256, 64, 64,
        1048576LL, 16384LL, 262144LL);

    // 11. fused depthwise conv residual + transpose to [b,n,inner] (rounded)
    conv_tr_kernel<<<65536, 256>>>(g_out_p, w_conv, g_outT_p);

    // 12. final fc: d_out = outT @ w_fc + b_fc   [16384,1024]@[1024,1024]
    tgemm3<false,false,true,false,false><<<dim3(8, 128, 1), 128, SMEM3>>>(
        g_outT_p, g_wfcr_p, dout, nullptr, 1024, 1024, 1024, 1024,
        0, 0, 0, 0.f, 1.f, b_fc, nullptr, nullptr, nullptr);
}

// round 16
// speedup vs baseline: 1.3133x; 1.2070x over previous
#include <cuda_runtime.h>
#include <cuda_fp16.h>
#include <cstdint>

// ============================================================================
// NystromAttention — R15 (tf32 + stream fork) with QKV & FC moved to fp16
// tensor cores (m16n8k16, NT, pre-transposed half weights).
// ============================================================================

// ---------------- scratch (device globals) ----------------------------------
__device__ __half g_xh   [16777216];  // x as half [16384][1024]
__device__ __half g_wqkvT[3145728];   // w_qkv^T half [3072][1024]
__device__ __half g_wfcT [1048576];   // w_fc^T half [1024][1024]
__device__ __half g_outTh[16777216];  // conv output half [b,n,1024]
__device__ float g_Q    [16777216];  // [b,h,n,d] scaled, rounded
__device__ float g_K    [16777216];
__device__ float g_V    [16777216];
__device__ float g_ql   [1048576];   // [bh, 256, 64]
__device__ float g_kl   [1048576];
__device__ float g_attn1[67108864];  // [bh, 4096, 256] (softmaxed)
__device__ float g_attn3[67108864];  // [bh, 256, 4096]
__device__ float g_attn2[4194304];   // [bh, 256, 256]
__device__ float g_z0   [4194304];
__device__ float g_z1   [4194304];
__device__ float g_az   [4194304];
__device__ float g_t2   [4194304];
__device__ float g_t4   [4194304];
__device__ float g_a3v  [1048576];   // [bh, 256, 64]
__device__ float g_tmp2 [1048576];   // [bh, 256, 64]
__device__ float g_out  [16777216];  // [b,h,n,d]
__device__ unsigned int g_m1, g_m2;

__device__ __forceinline__ unsigned f2tf(float f) {
    unsigned u;
    asm("cvt.rna.tf32.f32 %0, %1;" : "=r"(u) : "f"(f));
    return u;
}
__device__ __forceinline__ float rndtf(float f) {
    return __uint_as_float(f2tf(f));
}
__device__ __forceinline__ void cp16(unsigned d, const void* s) {
    asm volatile("cp.async.cg.shared.global [%0], [%1], 16;"
                 :: "r"(d), "l"(s) : "memory");
}
#define CP_COMMIT() asm volatile("cp.async.commit_group;" ::: "memory")
#define CP_WAIT0()  asm volatile("cp.async.wait_group 0;" ::: "memory")
#define CP_WAIT1()  asm volatile("cp.async.wait_group 1;" ::: "memory")

#define MMA_TF32(acc, a0,a1,a2,a3, b0,b1)                                     \
    asm volatile(                                                             \
        "mma.sync.aligned.m16n8k8.row.col.f32.tf32.tf32.f32 "                 \
        "{%0,%1,%2,%3}, {%4,%5,%6,%7}, {%8,%9}, {%0,%1,%2,%3};"               \
        : "+f"(acc[0]), "+f"(acc[1]), "+f"(acc[2]), "+f"(acc[3])              \
        : "r"(a0), "r"(a1), "r"(a2), "r"(a3), "r"(b0), "r"(b1))

#define MMA_F16(acc, a0,a1,a2,a3, b0,b1)                                      \
    asm volatile(                                                             \
        "mma.sync.aligned.m16n8k16.row.col.f32.f16.f16.f32 "                  \
        "{%0,%1,%2,%3}, {%4,%5,%6,%7}, {%8,%9}, {%0,%1,%2,%3};"               \
        : "+f"(acc[0]), "+f"(acc[1]), "+f"(acc[2]), "+f"(acc[3])              \
        : "r"(a0), "r"(a1), "r"(a2), "r"(a3), "r"(b0), "r"(b1))

// ============================================================================
// hgemm: fp16 NT GEMM. C = A(half,[M][K]) @ B^T(half,[N][K]) (+bias).
// CTA 128x128xBK64(halves), 4 warps (2x2) of 64x64, m16n8k16, 2-stage cp.async.
// QKVE: scatter epilogue to Q/K/V (fp32, tf32-rounded) — identical to tgemm3's.
// ============================================================================
static constexpr int H_AW = 128 * 36;   // half2 units per stage (A)
static constexpr int H_BW = 128 * 36;   // half2 units per stage (B)
static constexpr int SMEMH = (2 * H_AW + 2 * H_BW) * 4;  // 73728

template<bool BIAS, bool QKVE>
__global__ __launch_bounds__(128)
void hgemm(const __half* __restrict__ A, const __half* __restrict__ B,
           float* __restrict__ C, int Kdim, int lda, int ldb, int ldc,
           const float* __restrict__ bias,
           float* __restrict__ qp, float* __restrict__ kp,
           float* __restrict__ vp)
{
    extern __shared__ unsigned sh[];
    unsigned* Ash = sh;                // [2][128][36] half2
    unsigned* Bsh = sh + 2 * H_AW;     // [2][128][36] half2

    const int row0 = blockIdx.y * 128;
    const int col0 = blockIdx.x * 128;
    const int t    = threadIdx.x;
    const int lane = t & 31;
    const int w    = t >> 5;
    const int wm   = w & 1;
    const int wn   = w >> 1;
    const int g    = lane >> 2;
    const int tg   = lane & 3;

    const unsigned aBase = (unsigned)__cvta_generic_to_shared(Ash);
    const unsigned bBase = (unsigned)__cvta_generic_to_shared(Bsh);

    auto issue = [&](int k0, int st) {   // k0 in halves
        unsigned ab = aBase + st * (H_AW * 4);
        #pragma unroll
        for (int l = 0; l < 8; l++) {
            int c  = t + l * 128;        // 0..1023 chunks of 16B (8 halves)
            int r  = c >> 3;             // 0..127
            int ck = c & 7;              // chunk within row
            cp16(ab + (unsigned)(r * 36 + ck * 4) * 4,
                 A + (long long)(row0 + r) * lda + k0 + ck * 8);
        }
        unsigned bb = bBase + st * (H_BW * 4);
        #pragma unroll
        for (int l = 0; l < 8; l++) {
            int c  = t + l * 128;
            int r  = c >> 3;
            int ck = c & 7;
            cp16(bb + (unsigned)(r * 36 + ck * 4) * 4,
                 B + (long long)(col0 + r) * ldb + k0 + ck * 8);
        }
        CP_COMMIT();
    };

    float acc[4][8][4];
    #pragma unroll
    for (int mi = 0; mi < 4; mi++)
        #pragma unroll
        for (int ni = 0; ni < 8; ni++)
            #pragma unroll
            for (int q = 0; q < 4; q++) acc[mi][ni][q] = 0.f;

    issue(0, 0);

    int si = 0;
    for (int k0 = 0; k0 < Kdim; k0 += 64) {
        bool more = (k0 + 64 < Kdim);
        if (more) { issue(k0 + 64, si ^ 1); CP_WAIT1(); }
        else      { CP_WAIT0(); }
        __syncthreads();

        const unsigned* Ap = Ash + si * H_AW;
        const unsigned* Bp = Bsh + si * H_BW;
        #pragma unroll
        for (int ks = 0; ks < 4; ks++) {      // 4 x k16
            const int kk2 = ks * 8;            // half2 offset
            unsigned af[4][4], bf[8][2];
            #pragma unroll
            for (int mi = 0; mi < 4; mi++) {
                int rb = wm * 64 + mi * 16;
                af[mi][0] = Ap[(rb + g    ) * 36 + kk2 + tg];
                af[mi][1] = Ap[(rb + 8 + g) * 36 + kk2 + tg];
                af[mi][2] = Ap[(rb + g    ) * 36 + kk2 + 4 + tg];
                af[mi][3] = Ap[(rb + 8 + g) * 36 + kk2 + 4 + tg];
            }
            #pragma unroll
            for (int ni = 0; ni < 8; ni++) {
                int cb = wn * 64 + ni * 8;
                bf[ni][0] = Bp[(cb + g) * 36 + kk2 + tg];
                bf[ni][1] = Bp[(cb + g) * 36 + kk2 + 4 + tg];
            }
            #pragma unroll
            for (int mi = 0; mi < 4; mi++)
                #pragma unroll
                for (int ni = 0; ni < 8; ni++)
                    MMA_F16(acc[mi][ni],
                            af[mi][0], af[mi][1], af[mi][2], af[mi][3],
                            bf[ni][0], bf[ni][1]);
        }
        __syncthreads();
        si ^= 1;
    }

    // ---- epilogue (identical structure to tgemm3 QKVE / BIAS paths)
    #pragma unroll
    for (int mi = 0; mi < 4; mi++) {
        int r = row0 + wm * 64 + mi * 16 + g;
        #pragma unroll
        for (int ni = 0; ni < 8; ni++) {
            int c = col0 + wn * 64 + ni * 8 + 2 * tg;
            float v00 = acc[mi][ni][0], v01 = acc[mi][ni][1];
            float v10 = acc[mi][ni][2], v11 = acc[mi][ni][3];
            if (QKVE) {
                int which = c >> 10, hh = (c >> 6) & 15, d = c & 63;
                float sc = (which == 0) ? 0.125f : 1.f;
                float* dst = (which == 0) ? qp : ((which == 1) ? kp : vp);
                long long base =
                    (((long long)((r >> 12) * 16 + hh)) * 4096 + (r & 4095)) * 64 + d;
                *reinterpret_cast<float2*>(dst + base) =
                    make_float2(rndtf(v00 * sc), rndtf(v01 * sc));
                *reinterpret_cast<float2*>(dst + base + 512) =
                    make_float2(rndtf(v10 * sc), rndtf(v11 * sc));
                continue;
            }
            float b0 = 0.f, b1 = 0.f;
            if (BIAS) { b0 = bias[c]; b1 = bias[c + 1]; }
            *reinterpret_cast<float2*>(C + (long long)r * ldc + c) =
                make_float2(v00 + b0, v01 + b1);
            *reinterpret_cast<float2*>(C + (long long)(r + 8) * ldc + c) =
                make_float2(v10 + b0, v11 + b1);
        }
    }
}

// ============================================================================
// tgemm3 (exact R8): tf32, CTA 128x128x32, 4 warps of 64x64, 2-stage cp.async
// ============================================================================
static constexpr int AW = 128 * 36;
static constexpr int BW_NN = 32 * 136;
static constexpr int BW_NT = 128 * 36;
static constexpr int SMEM3 = (2 * AW + 2 * BW_NT) * 4;  // 73728

template<bool TRANSB, bool EPI, bool RND>
__global__ __launch_bounds__(128)
void tgemm3(const float* __restrict__ A, const float* __restrict__ B,
            float* __restrict__ C, const float* __restrict__ E,
            int Kdim, int lda, int ldb, int ldc,
            long long sA, long long sB, long long sC,
            float alpha, float outScale)
{
    constexpr int BW = TRANSB ? BW_NT : BW_NN;
    extern __shared__ unsigned sh[];
    unsigned* Ash = sh;
    unsigned* Bsh = sh + 2 * AW;

    const float* Ab = A + (long long)blockIdx.z * sA;
    const float* Bb = B + (long long)blockIdx.z * sB;
    float*       Cb = C + (long long)blockIdx.z * sC;
    const float* Eb = EPI ? (E + (long long)blockIdx.z * sC) : nullptr;

    const int row0 = blockIdx.y * 128;
    const int col0 = blockIdx.x * 128;
    const int t    = threadIdx.x;
    const int lane = t & 31;
    const int w    = t >> 5;
    const int wm   = w & 1;
    const int wn   = w >> 1;
    const int g    = lane >> 2;
    const int tg   = lane & 3;

    const unsigned aBase = (unsigned)__cvta_generic_to_shared(Ash);
    const unsigned bBase = (unsigned)__cvta_generic_to_shared(Bsh);

    auto issue = [&](int k0, int st) {
        unsigned ab = aBase + st * (AW * 4);
        #pragma unroll
        for (int l = 0; l < 8; l++) {
            int c  = t + l * 128;
            int r  = c >> 3;
            int kq = (c & 7) << 2;
            cp16(ab + (unsigned)(r * 36 + kq) * 4,
                 Ab + (long long)(row0 + r) * lda + k0 + kq);
        }
        unsigned bb = bBase + st * (BW * 4);
        #pragma unroll
        for (int l = 0; l < 8; l++) {
            int c = t + l * 128;
            if (!TRANSB) {
                int k  = c >> 5;
                int n4 = (c & 31) << 2;
                cp16(bb + (unsigned)(k * 136 + n4) * 4,
                     Bb + (long long)(k0 + k) * ldb + col0 + n4);
            } else {
                int j  = c >> 3;
                int kq = (c & 7) << 2;
                cp16(bb + (unsigned)(j * 36 + kq) * 4,
                     Bb + (long long)(col0 + j) * ldb + k0 + kq);
            }
        }
        CP_COMMIT();
    };

    float acc[4][8][4];
    #pragma unroll
    for (int mi = 0; mi < 4; mi++)
        #pragma unroll
        for (int ni = 0; ni < 8; ni++)
            #pragma unroll
            for (int q = 0; q < 4; q++) acc[mi][ni][q] = 0.f;

    issue(0, 0);

    int si = 0;
    for (int k0 = 0; k0 < Kdim; k0 += 32) {
        bool more = (k0 + 32 < Kdim);
        if (more) { issue(k0 + 32, si ^ 1); CP_WAIT1(); }
        else      { CP_WAIT0(); }
        __syncthreads();

        const unsigned* Ap = Ash + si * AW;
        const unsigned* Bp = Bsh + si * BW;
        #pragma unroll
        for (int ks = 0; ks < 4; ks++) {
            const int kk = ks * 8;
            unsigned af[4][4], bf[8][2];
            #pragma unroll
            for (int mi = 0; mi < 4; mi++) {
                int rb = wm * 64 + mi * 16;
                af[mi][0] = Ap[(rb + g    ) * 36 + kk + tg];
                af[mi][1] = Ap[(rb + 8 + g) * 36 + kk + tg];
                af[mi][2] = Ap[(rb + g    ) * 36 + kk + 4 + tg];
                af[mi][3] = Ap[(rb + 8 + g) * 36 + kk + 4 + tg];
            }
            #pragma unroll
            for (int ni = 0; ni < 8; ni++) {
                int cb = wn * 64 + ni * 8;
                if (TRANSB) {
                    bf[ni][0] = Bp[(cb + g) * 36 + kk + tg];
                    bf[ni][1] = Bp[(cb + g) * 36 + kk + 4 + tg];
                } else {
                    bf[ni][0] = Bp[(kk + tg) * 136 + cb + g];
                    bf[ni][1] = Bp[(kk + 4 + tg) * 136 + cb + g];
                }
            }
            #pragma unroll
            for (int mi = 0; mi < 4; mi++)
                #pragma unroll
                for (int ni = 0; ni < 8; ni++)
                    MMA_TF32(acc[mi][ni],
                             af[mi][0], af[mi][1], af[mi][2], af[mi][3],
                             bf[ni][0], bf[ni][1]);
        }
        __syncthreads();
        si ^= 1;
    }

    #pragma unroll
    for (int mi = 0; mi < 4; mi++) {
        int r = row0 + wm * 64 + mi * 16 + g;
        #pragma unroll
        for (int ni = 0; ni < 8; ni++) {
            int c = col0 + wn * 64 + ni * 8 + 2 * tg;
            float v00 = acc[mi][ni][0], v01 = acc[mi][ni][1];
            float v10 = acc[mi][ni][2], v11 = acc[mi][ni][3];
            if (EPI) {
                float2 e0 = *reinterpret_cast<const float2*>(
                    Eb + (long long)r * ldc + c);
                float2 e1 = *reinterpret_cast<const float2*>(
                    Eb + (long long)(r + 8) * ldc + c);
                v00 = (alpha * e0.x - v00) * outScale;
                v01 = (alpha * e0.y - v01) * outScale;
                v10 = (alpha * e1.x - v10) * outScale;
                v11 = (alpha * e1.y - v11) * outScale;
            } else {
                v00 *= outScale; v01 *= outScale;
                v10 *= outScale; v11 *= outScale;
            }
            if (RND) {
                v00 = rndtf(v00); v01 = rndtf(v01);
                v10 = rndtf(v10); v11 = rndtf(v11);
            }
            *reinterpret_cast<float2*>(Cb + (long long)r * ldc + c) =
                make_float2(v00, v01);
            *reinterpret_cast<float2*>(Cb + (long long)(r + 8) * ldc + c) =
                make_float2(v10, v11);
        }
    }
}

// ============================================================================
// sim1s (exact R13): attn1 = softmax(Q @ kl^T), 64 full rows per CTA
// ============================================================================
static constexpr int S_AW = 2 * 64 * 36;
static constexpr int S_BW = 2 * 256 * 36;
static constexpr int SMEMS = (S_AW + S_BW) * 4;   // 92160

__global__ __launch_bounds__(256, 2)
void sim1s(const float* __restrict__ Q, const float* __restrict__ KL,
           float* __restrict__ OUT)
{
    extern __shared__ unsigned sh[];
    unsigned* Ash = sh;
    unsigned* Bsh = sh + S_AW;
    unsigned* Ss  = Bsh;

    const int bh   = blockIdx.y;
    const int row0 = blockIdx.x * 64;
    const int t    = threadIdx.x;
    const int lane = t & 31;
    const int w    = t >> 5;
    const int wm   = w & 1;
    const int wn   = w >> 1;
    const int g    = lane >> 2;
    const int tg   = lane & 3;

    const float* Qb  = Q  + (long long)bh * 262144 + (long long)row0 * 64;
    const float* KLb = KL + (long long)bh * 16384;
    float*       Ob  = OUT + (long long)bh * 1048576 + (long long)row0 * 256;

    const unsigned aBase = (unsigned)__cvta_generic_to_shared(Ash);
    const unsigned bBase = (unsigned)__cvta_generic_to_shared(Bsh);

    #pragma unroll
    for (int l = 0; l < 4; l++) {
        int idx = t + l * 256;
        int r  = idx >> 4;
        int k0 = (idx & 15) << 2;
        cp16(aBase + (unsigned)((k0 >> 5) * 2304 + r * 36 + (k0 & 31)) * 4,
             Qb + r * 64 + k0);
    }
    #pragma unroll
    for (int l = 0; l < 16; l++) {
        int idx = t + l * 256;
        int n  = idx >> 4;
        int k0 = (idx & 15) << 2;
        cp16(bBase + (unsigned)((k0 >> 5) * 9216 + n * 36 + (k0 & 31)) * 4,
             KLb + n * 64 + k0);
    }
    CP_COMMIT();
    CP_WAIT0();
    __syncthreads();

    float acc[2][8][4];
    #pragma unroll
    for (int mi = 0; mi < 2; mi++)
        #pragma unroll
        for (int ni = 0; ni < 8; ni++)
            #pragma unroll
            for (int q = 0; q < 4; q++) acc[mi][ni][q] = 0.f;

    #pragma unroll
    for (int ch = 0; ch < 2; ch++) {
        const unsigned* Ap = Ash + ch * 2304;
        const unsigned* Bp = Bsh + ch * 9216;
        #pragma unroll
        for (int ks = 0; ks < 4; ks++) {
            const int kk = ks * 8;
            unsigned af[2][4], bf[8][2];
            #pragma unroll
            for (int mi = 0; mi < 2; mi++) {
                int rb = wm * 32 + mi * 16;
                af[mi][0] = Ap[(rb + g    ) * 36 + kk + tg];
                af[mi][1] = Ap[(rb + 8 + g) * 36 + kk + tg];
                af[mi][2] = Ap[(rb + g    ) * 36 + kk + 4 + tg];
                af[mi][3] = Ap[(rb + 8 + g) * 36 + kk + 4 + tg];
            }
            #pragma unroll
            for (int ni = 0; ni < 8; ni++) {
                int cb = wn * 64 + ni * 8;
                bf[ni][0] = Bp[(cb + g) * 36 + kk + tg];
                bf[ni][1] = Bp[(cb + g) * 36 + kk + 4 + tg];
            }
            #pragma unroll
            for (int mi = 0; mi < 2; mi++)
                #pragma unroll
                for (int ni = 0; ni < 8; ni++)
                    MMA_TF32(acc[mi][ni],
                             af[mi][0], af[mi][1], af[mi][2], af[mi][3],
                             bf[ni][0], bf[ni][1]);
        }
    }
    __syncthreads();

    #pragma unroll
    for (int mi = 0; mi < 2; mi++) {
        int r = wm * 32 + mi * 16 + g;
        #pragma unroll
        for (int ni = 0; ni < 8; ni++) {
            int c = wn * 64 + ni * 8 + 2 * tg;
            unsigned* p0 = Ss + r * 260 + c;
            p0[0] = __float_as_uint(acc[mi][ni][0]);
            p0[1] = __float_as_uint(acc[mi][ni][1]);
            unsigned* p1 = Ss + (r + 8) * 260 + c;
            p1[0] = __float_as_uint(acc[mi][ni][2]);
            p1[1] = __float_as_uint(acc[mi][ni][3]);
        }
    }
    __syncthreads();

    #pragma unroll
    for (int rr = 0; rr < 8; rr++) {
        int r = w * 8 + rr;
        float v[8];
        float mx = -1e30f;
        #pragma unroll
        for (int i = 0; i < 8; i++) {
            v[i] = __uint_as_float(Ss[r * 260 + lane + 32 * i]);
            mx = fmaxf(mx, v[i]);
        }
        #pragma unroll
        for (int o = 16; o > 0; o >>= 1)
            mx = fmaxf(mx, __shfl_xor_sync(0xffffffffu, mx, o));
        float s = 0.f;
        #pragma unroll
        for (int i = 0; i < 8; i++) { v[i] = expf(v[i] - mx); s += v[i]; }
        #pragma unroll
        for (int o = 16; o > 0; o >>= 1)
            s += __shfl_xor_sync(0xffffffffu, s, o);
        float inv = 1.f / s;
        #pragma unroll
        for (int i = 0; i < 8; i++)
            Ob[r * 256 + lane + 32 * i] = rndtf(v[i] * inv);
    }
}

// ============================================================================
// tgemm: tf32 CTA 128x64x32, 8 warps (4x2), warp 32x32 — N=64 tails
// ============================================================================
template<bool SPLITK>
__global__ __launch_bounds__(256)
void tgemm(const float* __restrict__ A, const float* __restrict__ B,
           float* __restrict__ C, int Kdim, int lda, int ldb, int ldc,
           long long sA, long long sB, long long sC)
{
    extern __shared__ unsigned sh[];
    unsigned* As = sh;
    unsigned* Bs = sh + 2 * 4608;

    const float* Ab;
    const float* Bb;
    float*       Cb;
    if (SPLITK) {
        int bh = blockIdx.z >> 3, ks = blockIdx.z & 7;
        Ab = A + (long long)bh * sA + (long long)ks * Kdim;
        Bb = B + (long long)bh * sB + (long long)ks * Kdim * ldb;
        Cb = C + (long long)bh * sC;
    } else {
        Ab = A + (long long)blockIdx.z * sA;
        Bb = B + (long long)blockIdx.z * sB;
        Cb = C + (long long)blockIdx.z * sC;
    }

    const int row0 = blockIdx.y * 128;
    const int col0 = blockIdx.x * 64;
    const int t    = threadIdx.x;
    const int lane = t & 31;
    const int w    = t >> 5;
    const int wm   = w & 3;
    const int wn   = w >> 2;
    const int g    = lane >> 2;
    const int tg   = lane & 3;

    float4 aR[4];
    float4 bR[2];

    auto ldA = [&](int k0) {
        #pragma unroll
        for (int l = 0; l < 4; l++) {
            int idx = t + l * 256;
            int r   = idx >> 3;
            int kq  = (idx & 7) << 2;
            aR[l] = *reinterpret_cast<const float4*>(
                Ab + (long long)(row0 + r) * lda + k0 + kq);
        }
    };
    auto stA = [&](int st) {
        unsigned* Ap = As + st * 4608;
        #pragma unroll
        for (int l = 0; l < 4; l++) {
            int idx = t + l * 256;
            int r   = idx >> 3;
            int kq  = (idx & 7) << 2;
            uint4 u = make_uint4(f2tf(aR[l].x), f2tf(aR[l].y),
                                 f2tf(aR[l].z), f2tf(aR[l].w));
            *reinterpret_cast<uint4*>(Ap + r * 36 + kq) = u;
        }
    };
    auto ldB = [&](int k0) {
        #pragma unroll
        for (int l = 0; l < 2; l++) {
            int idx = t + l * 256;
            int r  = idx >> 4;
            int cq = (idx & 15) << 2;
            bR[l] = *reinterpret_cast<const float4*>(
                Bb + (long long)(k0 + r) * ldb + col0 + cq);
        }
    };
    auto stB = [&](int st) {
        unsigned* Bp = Bs + st * 2304;
        #pragma unroll
        for (int l = 0; l < 2; l++) {
            int idx = t + l * 256;
            int r  = idx >> 4;
            int cq = (idx & 15) << 2;
            uint4 u = make_uint4(f2tf(bR[l].x), f2tf(bR[l].y),
                                 f2tf(bR[l].z), f2tf(bR[l].w));
            *reinterpret_cast<uint4*>(Bp + r * 72 + cq) = u;
        }
    };

    float acc[2][4][4];
    #pragma unroll
    for (int mi = 0; mi < 2; mi++)
        #pragma unroll
        for (int ni = 0; ni < 4; ni++)
            #pragma unroll
            for (int q = 0; q < 4; q++) acc[mi][ni][q] = 0.f;

    ldA(0); ldB(0);
    stA(0); stB(0);
    __syncthreads();

    int s = 0;
    for (int k0 = 0; k0 < Kdim; k0 += 32) {
        bool more = (k0 + 32 < Kdim);
        if (more) { ldA(k0 + 32); ldB(k0 + 32); }

        const unsigned* Ap = As + s * 4608;
        const unsigned* Bp = Bs + s * 2304;
        #pragma unroll
        for (int ks = 0; ks < 4; ks++) {
            const int kk = ks * 8;
            unsigned af[2][4], bf[4][2];
            #pragma unroll
            for (int mi = 0; mi < 2; mi++) {
                int rb = wm * 32 + mi * 16;
                af[mi][0] = Ap[(rb + g    ) * 36 + kk + tg];
                af[mi][1] = Ap[(rb + 8 + g) * 36 + kk + tg];
                af[mi][2] = Ap[(rb + g    ) * 36 + kk + 4 + tg];
                af[mi][3] = Ap[(rb + 8 + g) * 36 + kk + 4 + tg];
            }
            #pragma unroll
            for (int ni = 0; ni < 4; ni++) {
                int cb = wn * 32 + ni * 8;
                bf[ni][0] = Bp[(kk + tg) * 72 + cb + g];
                bf[ni][1] = Bp[(kk + 4 + tg) * 72 + cb + g];
            }
            #pragma unroll
            for (int mi = 0; mi < 2; mi++)
                #pragma unroll
                for (int ni = 0; ni < 4; ni++)
                    MMA_TF32(acc[mi][ni],
                             af[mi][0], af[mi][1], af[mi][2], af[mi][3],
                             bf[ni][0], bf[ni][1]);
        }

        if (more) {
            stA(s ^ 1); stB(s ^ 1);
            __syncthreads();
        }
        s ^= 1;
    }

    #pragma unroll
    for (int mi = 0; mi < 2; mi++) {
        int r = row0 + wm * 32 + mi * 16 + g;
        #pragma unroll
        for (int ni = 0; ni < 4; ni++) {
            int c = col0 + wn * 32 + ni * 8 + 2 * tg;
            if (SPLITK) {
                float* p0 = Cb + (long long)r * ldc + c;
                atomicAdd(p0,                          acc[mi][ni][0]);
                atomicAdd(p0 + 1,                      acc[mi][ni][1]);
                atomicAdd(p0 + (long long)8 * ldc,     acc[mi][ni][2]);
                atomicAdd(p0 + (long long)8 * ldc + 1, acc[mi][ni][3]);
            } else {
                *reinterpret_cast<float2*>(Cb + (long long)r * ldc + c) =
                    make_float2(acc[mi][ni][0], acc[mi][ni][1]);
                *reinterpret_cast<float2*>(Cb + (long long)(r + 8) * ldc + c) =
                    make_float2(acc[mi][ni][2], acc[mi][ni][3]);
            }
        }
    }
}

// ---------------- elementwise / reductions ---------------------------------
// float -> half copy (for x)
__global__ void xh_kernel(const float* __restrict__ src,
                          __half* __restrict__ dst, int n4)
{
    int i = blockIdx.x * 256 + threadIdx.x;
    if (i >= n4) return;
    float4 v = reinterpret_cast<const float4*>(src)[i];
    __half2 h0 = __floats2half2_rn(v.x, v.y);
    __half2 h1 = __floats2half2_rn(v.z, v.w);
    uint2 u = make_uint2(*reinterpret_cast<unsigned*>(&h0),
                         *reinterpret_cast<unsigned*>(&h1));
    reinterpret_cast<uint2*>(dst)[i] = u;
}

// tiled transpose: src fp32 [Kd][Nd] -> dst half [Nd][Kd]
__global__ void wt_kernel(const float* __restrict__ src,
                          __half* __restrict__ dst, int Kd, int Nd)
{
    __shared__ float sm[32][33];
    int kt = blockIdx.y, nt = blockIdx.x;
    int t  = threadIdx.x;
    int tx = t & 31, ty = t >> 5;   // 8 rows per pass
    #pragma unroll
    for (int l = 0; l < 4; l++) {
        int r = l * 8 + ty;
        sm[r][tx] = src[(long long)(kt * 32 + r) * Nd + nt * 32 + tx];
    }
    __syncthreads();
    #pragma unroll
    for (int l = 0; l < 4; l++) {
        int r = l * 8 + ty;
        dst[(long long)(nt * 32 + r) * Kd + kt * 32 + tx] =
            __float2half_rn(sm[tx][r]);
    }
}

__global__ void landmarks_kernel(const float* __restrict__ Q,
                                 const float* __restrict__ K,
                                 float* __restrict__ ql, float* __restrict__ kl)
{
    int i = blockIdx.x * 256 + threadIdx.x;
    int d = i & 63;
    int m = (i >> 6) & 255;
    int bh = i >> 14;
    long long base = ((long long)bh * 4096 + m * 16) * 64 + d;
    float sq = 0.f, sk = 0.f;
    #pragma unroll
    for (int j = 0; j < 16; j++) {
        sq += Q[base + j * 64];
        sk += K[base + j * 64];
    }
    ql[i] = rndtf(sq * 0.0625f);
    kl[i] = rndtf(sk * 0.0625f);
}

__global__ void softmax256_kernel(float* __restrict__ data, int rows)
{
    int gw   = (int)((blockIdx.x * (long long)blockDim.x + threadIdx.x) >> 5);
    int lane = threadIdx.x & 31;
    if (gw >= rows) return;
    float* p = data + (long long)gw * 256;
    float v[8];
    float mx = -1e30f;
    #pragma unroll
    for (int i = 0; i < 8; i++) { v[i] = p[lane + 32 * i]; mx = fmaxf(mx, v[i]); }
    #pragma unroll
    for (int o = 16; o > 0; o >>= 1) mx = fmaxf(mx, __shfl_xor_sync(0xffffffffu, mx, o));
    float s = 0.f;
    #pragma unroll
    for (int i = 0; i < 8; i++) { v[i] = expf(v[i] - mx); s += v[i]; }
    #pragma unroll
    for (int o = 16; o > 0; o >>= 1) s += __shfl_xor_sync(0xffffffffu, s, o);
    float inv = 1.f / s;
    #pragma unroll
    for (int i = 0; i < 8; i++) p[lane + 32 * i] = rndtf(v[i] * inv);
}

__global__ void softmax4096_kernel(float* __restrict__ data)
{
    float* p = data + (long long)blockIdx.x * 4096;
    int t = threadIdx.x;
    float v[16];
    float mx = -1e30f;
    #pragma unroll
    for (int i = 0; i < 16; i++) { v[i] = p[t + 256 * i]; mx = fmaxf(mx, v[i]); }
    __shared__ float red[256];
    red[t] = mx; __syncthreads();
    for (int s = 128; s > 0; s >>= 1) {
        if (t < s) red[t] = fmaxf(red[t], red[t + s]);
        __syncthreads();
    }
    mx = red[0]; __syncthreads();
    float sum = 0.f;
    #pragma unroll
    for (int i = 0; i < 16; i++) { v[i] = expf(v[i] - mx); sum += v[i]; }
    red[t] = sum; __syncthreads();
    for (int s = 128; s > 0; s >>= 1) {
        if (t < s) red[t] += red[t + s];
        __syncthreads();
    }
    float inv = 1.f / red[0];
    #pragma unroll
    for (int i = 0; i < 16; i++) p[t + 256 * i] = rndtf(v[i] * inv);
}

__global__ void mp_reset_kernel() { g_m1 = 0u; g_m2 = 0u; }

__global__ void mp_reduce_kernel(const float* __restrict__ a)
{
    int bh = blockIdx.x;
    int j  = threadIdx.x;
    const float* p = a + (long long)bh * 65536;
    float rs = 0.f, cs = 0.f;
    for (int i = 0; i < 256; i++) {
        rs += fabsf(p[j * 256 + i]);
        cs += fabsf(p[i * 256 + j]);
    }
    __shared__ float r1[256], r2[256];
    r1[j] = rs; r2[j] = cs; __syncthreads();
    for (int s = 128; s > 0; s >>= 1) {
        if (j < s) { r1[j] = fmaxf(r1[j], r1[j + s]); r2[j] = fmaxf(r2[j], r2[j + s]); }
        __syncthreads();
    }
    if (j == 0) {
        atomicMax(&g_m1, __float_as_uint(r1[0]));
        atomicMax(&g_m2, __float_as_uint(r2[0]));
    }
}

__global__ void mp_init_kernel(const float* __restrict__ a, float* __restrict__ z)
{
    long long i = (long long)blockIdx.x * 256 + threadIdx.x;
    int col = (int)(i & 255);
    int row = (int)((i >> 8) & 255);
    long long bh = i >> 16;
    float denom = __uint_as_float(g_m1) * __uint_as_float(g_m2);
    z[i] = rndtf(a[bh * 65536 + (long long)col * 256 + row] / denom);
}

// fused: depthwise residual conv + transpose -> half [b,n,h*64+d]
__global__ void conv_tr_kernel(const float* __restrict__ src,
                               const float* __restrict__ w,
                               __half* __restrict__ dst)
{
    long long o = (long long)blockIdx.x * 256 + threadIdx.x;
    int d = (int)(o & 63);
    int h = (int)((o >> 6) & 15);
    int n = (int)((o >> 10) & 4095);
    int b = (int)(o >> 22);
    long long s = (((long long)(b * 16 + h)) * 4096 + n) * 64 + d;
    float v = src[s];
    float r = 0.f;
    #pragma unroll
    for (int tt = 0; tt < 13; tt++) {
        int nn = n + tt - 6;
        if (nn >= 0 && nn < 4096)
            r += w[h * 13 + tt] * src[s + (long long)(tt - 6) * 64];
    }
    dst[o] = __float2half_rn(v + r);
}

// ---------------- launch ----------------------------------------------------
static constexpr int SMEM1 = (2 * 4608 + 2 * 2304) * 4;  // 55296 (tgemm)

extern "C" void kernel_launch(void* const* d_in, const int* in_sizes, int n_in,
                              void* d_out, int out_size)
{
    (void)in_sizes; (void)n_in; (void)out_size;
    const float* x      = (const float*)d_in[0];
    const float* w_qkv  = (const float*)d_in[1];
    const float* w_conv = (const float*)d_in[2];
    const float* w_fc   = (const float*)d_in[3];
    const float* b_fc   = (const float*)d_in[4];
    float* dout = (float*)d_out;

    void* vp_;
    #define SYMPT(T, nm) T* nm##_p; cudaGetSymbolAddress(&vp_, nm); nm##_p = (T*)vp_;
    SYMPT(__half, g_xh)   SYMPT(__half, g_wqkvT) SYMPT(__half, g_wfcT)
    SYMPT(__half, g_outTh)
    SYMPT(float, g_Q)    SYMPT(float, g_K)    SYMPT(float, g_V)
    SYMPT(float, g_ql)   SYMPT(float, g_kl)
    SYMPT(float, g_attn1) SYMPT(float, g_attn3) SYMPT(float, g_attn2)
    SYMPT(float, g_z0)   SYMPT(float, g_z1)   SYMPT(float, g_az)
    SYMPT(float, g_t2)   SYMPT(float, g_t4)
    SYMPT(float, g_a3v)  SYMPT(float, g_tmp2)
    SYMPT(float, g_out)
    #undef SYMPT

    cudaFuncSetAttribute(hgemm<false,true >,
                         cudaFuncAttributeMaxDynamicSharedMemorySize, SMEMH);
    cudaFuncSetAttribute(hgemm<true ,false>,
                         cudaFuncAttributeMaxDynamicSharedMemorySize, SMEMH);
    cudaFuncSetAttribute(tgemm3<true ,false,false>,
                         cudaFuncAttributeMaxDynamicSharedMemorySize, SMEM3);
    cudaFuncSetAttribute(tgemm3<false,false,true >,
                         cudaFuncAttributeMaxDynamicSharedMemorySize, SMEM3);
    cudaFuncSetAttribute(tgemm3<false,true ,true >,
                         cudaFuncAttributeMaxDynamicSharedMemorySize, SMEM3);
    cudaFuncSetAttribute(tgemm<false>,
                         cudaFuncAttributeMaxDynamicSharedMemorySize, SMEM1);
    cudaFuncSetAttribute(tgemm<true>,
                         cudaFuncAttributeMaxDynamicSharedMemorySize, SMEM1);
    cudaFuncSetAttribute(sim1s,
                         cudaFuncAttributeMaxDynamicSharedMemorySize, SMEMS);

    static cudaStream_t s1 = nullptr;
    static cudaEvent_t evF = nullptr, evJ = nullptr;
    if (s1 == nullptr) {
        cudaStreamCreateWithFlags(&s1, cudaStreamNonBlocking);
        cudaEventCreateWithFlags(&evF, cudaEventDisableTiming);
        cudaEventCreateWithFlags(&evJ, cudaEventDisableTiming);
    }

    // 0. prepare fp16 GEMM inputs: x -> half; w_qkv^T, w_fc^T -> half
    xh_kernel<<<16384, 256>>>(x, g_xh_p, 4194304);
    wt_kernel<<<dim3(96, 32), 256>>>(w_qkv, g_wqkvT_p, 1024, 3072);
    wt_kernel<<<dim3(32, 32), 256>>>(w_fc, g_wfcT_p, 1024, 1024);

    // 1. qkv projection (fp16 NT) fused with split+scale+round -> g_Q/g_K/g_V
    hgemm<false,true><<<dim3(24, 128, 1), 128, SMEMH>>>(
        g_xh_p, g_wqkvT_p, nullptr, 1024, 1024, 1024, 0,
        nullptr, g_Q_p, g_K_p, g_V_p);

    // 2. landmarks (rounded)
    landmarks_kernel<<<4096, 256>>>(g_Q_p, g_K_p, g_ql_p, g_kl_p);

    // ---- fork: MP chain on s1, attn chains on default stream --------------
    cudaEventRecord(evF, 0);
    cudaStreamWaitEvent(s1, evF, 0);

    // [s1] sim2 = ql @ kl^T
    tgemm3<true,false,false><<<dim3(2, 2, 64), 128, SMEM3, s1>>>(
        g_ql_p, g_kl_p, g_attn2_p, nullptr, 64, 64, 64, 256,
        16384LL, 16384LL, 65536LL, 0.f, 1.f);
    softmax256_kernel<<<2048, 256, 0, s1>>>(g_attn2_p, 16384);
    mp_reset_kernel<<<1, 1, 0, s1>>>();
    mp_reduce_kernel<<<64, 256, 0, s1>>>(g_attn2_p);
    mp_init_kernel<<<16384, 256, 0, s1>>>(g_attn2_p, g_z0_p);
    float* zin = g_z0_p; float* zout = g_z1_p;
    for (int it = 0; it < 6; it++) {
        tgemm3<false,false,true><<<dim3(2, 2, 64), 128, SMEM3, s1>>>(
            g_attn2_p, zin, g_az_p, nullptr, 256, 256, 256, 256,
            65536LL, 65536LL, 65536LL, 0.f, 1.f);
        tgemm3<false,true,true><<<dim3(2, 2, 64), 128, SMEM3, s1>>>(
            g_az_p, g_az_p, g_t2_p, g_az_p, 256, 256, 256, 256,
            65536LL, 65536LL, 65536LL, 7.f, 1.f);
        tgemm3<false,true,true><<<dim3(2, 2, 64), 128, SMEM3, s1>>>(
            g_az_p, g_t2_p, g_t4_p, g_az_p, 256, 256, 256, 256,
            65536LL, 65536LL, 65536LL, 15.f, 1.f);
        tgemm3<false,true,true><<<dim3(2, 2, 64), 128, SMEM3, s1>>>(
            zin, g_t4_p, zout, zin, 256, 256, 256, 256,
            65536LL, 65536LL, 65536LL, 13.f, 0.25f);
        float* tmp = zin; zin = zout; zout = tmp;
    }
    cudaEventRecord(evJ, s1);

    // [default] attn1 = softmax(Q @ kl^T)
    sim1s<<<dim3(64, 64), 256, SMEMS>>>(g_Q_p, g_kl_p, g_attn1_p);

    // [default] sim3 = ql @ K^T
    tgemm3<true,false,false><<<dim3(32, 2, 64), 128, SMEM3>>>(
        g_ql_p, g_K_p, g_attn3_p, nullptr, 64, 64, 64, 4096,
        16384LL, 262144LL, 1048576LL, 0.f, 1.f);

    // [default] softmax attn3
    softmax4096_kernel<<<16384, 256>>>(g_attn3_p);

    // [default] a3v = attn3 @ V, split-K x8 atomic epilogue
    cudaMemsetAsync(g_a3v_p, 0, 1048576 * sizeof(float));
    tgemm<true><<<dim3(1, 2, 512), 256, SMEM1>>>(
        g_attn3_p, g_V_p, g_a3v_p, 512, 4096, 64, 64,
        1048576LL, 262144LL, 16384LL);

    // ---- join
    cudaStreamWaitEvent(0, evJ, 0);

    // 9. tmp2 = z @ a3v
    tgemm<false><<<dim3(1, 2, 64), 256, SMEM1>>>(
        zin, g_a3v_p, g_tmp2_p, 256, 256, 64, 64,
        65536LL, 16384LL, 16384LL);

    // 10. out = attn1 @ tmp2
    tgemm<false><<<dim3(1, 32, 64), 256, SMEM1>>>(
        g_attn1_p, g_tmp2_p, g_out_p, 256, 256, 64, 64,
        1048576LL, 16384LL, 262144LL);

    // 11. fused depthwise conv residual + transpose -> half [b,n,inner]
    conv_tr_kernel<<<65536, 256>>>(g_out_p, w_conv, g_outTh_p);

    // 12. final fc (fp16 NT): d_out = outT @ w_fc + b_fc
    hgemm<true,false><<<dim3(8, 128, 1), 128, SMEMH>>>(
        g_outTh_p, g_wfcT_p, dout, 1024, 1024, 1024, 1024,
        b_fc, nullptr, nullptr, nullptr);
}